// round 5
// baseline (speedup 1.0000x reference)
#include <cuda_runtime.h>
#include <math.h>

typedef unsigned long long u64;

// ---------------------------------------------------------------------------
// Device-global scratch (allocation-free contract: module globals only)
// Hidden-state rings are slot-major [slot][B][H]; slot 0 = initial state,
// slot s+1 = output of step s. Round-unique addresses -> no stale-L1 hazard.
// ---------------------------------------------------------------------------
__device__ __align__(256) float g_h0all[513 * 256 * 256];  // layer0 h ring (~128MB)
__device__ __align__(256) float g_h1all[513 * 256 * 256];  // layer1 h ring (~128MB)
__device__ __align__(256) float g_c0[256 * 256];
__device__ __align__(256) float g_c1[256 * 256];
__device__ __align__(256) float g_x0[256 * 256];
__device__ __align__(256) float g_gx0[256 * 1024];         // x proj + b_ih0 + b_hh0
__device__ __align__(256) float g_b1sum[1024];             // b_ih1 + b_hh1
__device__ unsigned g_bar_arrive;
__device__ volatile unsigned g_bar_release;

// ---------------------------------------------------------------------------
// PTX helpers
// ---------------------------------------------------------------------------
#define CPA8(s, g)  asm volatile("cp.async.ca.shared.global [%0], [%1], 8;" :: "r"(s), "l"(g))
#define CPCOMMIT()  asm volatile("cp.async.commit_group;")
#define CPWAIT1()   asm volatile("cp.async.wait_group 1;")
#define CPWAIT0()   asm volatile("cp.async.wait_group 0;")
#define FMA2(d, a, b) asm("fma.rn.f32x2 %0, %1, %2, %0;" : "+l"(d) : "l"(a), "l"(b))

__device__ __forceinline__ float sum2(u64 v) {
    float lo, hi;
    asm("mov.b64 {%0,%1}, %2;" : "=f"(lo), "=f"(hi) : "l"(v));
    return lo + hi;
}
__device__ __forceinline__ float sigf(float x) {
    x = fminf(fmaxf(x, -30.f), 30.f);
    return 1.f / (1.f + __expf(-x));
}
__device__ __forceinline__ float tanhfast(float x) {
    x = fminf(fmaxf(x, -15.f), 15.f);
    float e = __expf(2.f * x);
    return (e - 1.f) / (e + 1.f);
}

// Software grid barrier (all 128 CTAs co-resident; round is 1-based, counters
// reset by init_gx0 each launch).
__device__ __forceinline__ void grid_sync(unsigned round) {
    __syncthreads();
    if (threadIdx.x == 0) {
        __threadfence();
        unsigned old = atomicAdd(&g_bar_arrive, 1u);
        if (old + 1u == round * gridDim.x) {
            g_bar_release = round;
            __threadfence();
        } else {
            while (g_bar_release < round) __nanosleep(32);
            __threadfence();
        }
    }
    __syncthreads();
}

// ---------------------------------------------------------------------------
// GEMM tile machinery. CTA computes C[32 batch x 64 gate-cols], K=256,
// k-tiles of 32 floats (16 u64). Smem pitch 17 u64 -> conflict-free wv reads.
// Thread (tb=tid>>4, tc=tid&15) owns rows tb*4..+3, cols {tc+16g} (all 4
// gates of hidden unit j0+tc) -> pointwise is register-local.
// ---------------------------------------------------------------------------
__device__ __forceinline__ void issue_tile(
    int t, int NW, const u64* __restrict__ Hg,
    const u64* __restrict__ W0, const u64* __restrict__ W1,
    unsigned hs_sa, unsigned ws_sa, int b0, int j0, int tid)
{
    const int u = t & 1;
    const int kb = t * 16;
#pragma unroll
    for (int q = 0; q < 4; ++q) {
        int idx = tid + (q << 7);
        int hr = idx >> 4, hk = idx & 15;
        CPA8(hs_sa + (unsigned)(u * 544 + hr * 17 + hk) * 8u,
             Hg + (unsigned)(b0 + hr) * 128u + kb + hk);
    }
#pragma unroll
    for (int q = 0; q < 8; ++q) {
        int idx = tid + (q << 7);
        int wc = idx >> 4, wk = idx & 15;
        int wrow = ((wc >> 4) << 8) + j0 + (wc & 15);   // gate*256 + j
        CPA8(ws_sa + (unsigned)((u * 2 + 0) * 1088 + wc * 17 + wk) * 8u,
             W0 + (unsigned)wrow * 128u + kb + wk);
        if (NW == 2)
            CPA8(ws_sa + (unsigned)((u * 2 + 1) * 1088 + wc * 17 + wk) * 8u,
                 W1 + (unsigned)wrow * 128u + kb + wk);
    }
    CPCOMMIT();
}

__device__ __forceinline__ void compute_tile(
    int t, int NW, u64 (&a0)[4][4], u64 (&a1)[4][4],
    const u64* __restrict__ Hsm, const u64* __restrict__ Wsm, int tid)
{
    const int u = t & 1;
    const u64* hb = Hsm + u * 544;
    const u64* w0 = Wsm + (u * 2 + 0) * 1088;
    const u64* w1 = Wsm + (u * 2 + 1) * 1088;
    const int tc = tid & 15;
    const int tb4 = (tid >> 4) << 2;
#pragma unroll
    for (int kk = 0; kk < 16; ++kk) {
        u64 hv[4];
#pragma unroll
        for (int i = 0; i < 4; ++i) hv[i] = hb[(tb4 + i) * 17 + kk];
        u64 wv[4];
#pragma unroll
        for (int g = 0; g < 4; ++g) wv[g] = w0[(g * 16 + tc) * 17 + kk];
#pragma unroll
        for (int i = 0; i < 4; ++i)
#pragma unroll
            for (int g = 0; g < 4; ++g) FMA2(a0[i][g], hv[i], wv[g]);
        if (NW == 2) {
#pragma unroll
            for (int g = 0; g < 4; ++g) wv[g] = w1[(g * 16 + tc) * 17 + kk];
#pragma unroll
            for (int i = 0; i < 4; ++i)
#pragma unroll
                for (int g = 0; g < 4; ++g) FMA2(a1[i][g], hv[i], wv[g]);
        }
    }
}

__device__ __forceinline__ void gemm_run(
    int NW, u64 (&a0)[4][4], u64 (&a1)[4][4],
    const u64* __restrict__ Hg,
    const u64* __restrict__ W0, const u64* __restrict__ W1,
    const u64* Hsm, const u64* Wsm,
    unsigned hs_sa, unsigned ws_sa, int b0, int j0, int tid)
{
    issue_tile(0, NW, Hg, W0, W1, hs_sa, ws_sa, b0, j0, tid);
#pragma unroll 1
    for (int t = 0; t < 8; ++t) {
        if (t < 7) {
            issue_tile(t + 1, NW, Hg, W0, W1, hs_sa, ws_sa, b0, j0, tid);
            CPWAIT1();
        } else {
            CPWAIT0();
        }
        __syncthreads();
        compute_tile(t, NW, a0, a1, Hsm, Wsm, tid);
        __syncthreads();
    }
}

// ---------------------------------------------------------------------------
// Init kernel 1: initial hidden/cell states + x0 (z-projections)
// ---------------------------------------------------------------------------
__global__ void __launch_bounds__(256) init_states(
    const float* __restrict__ z,
    const float* __restrict__ Wh, const float* __restrict__ bh,
    const float* __restrict__ Wc, const float* __restrict__ bc,
    const float* __restrict__ Wx, const float* __restrict__ bx)
{
    __shared__ float zs[128];
    const int b = blockIdx.x, tid = threadIdx.x;
    if (tid < 128) zs[tid] = z[b * 128 + tid];
    __syncthreads();
#pragma unroll
    for (int rep = 0; rep < 2; ++rep) {
        int c = tid + (rep << 8);
        float sh = bh[c], sc = bc[c];
        const float4* wh4 = (const float4*)(Wh + c * 128);
        const float4* wc4 = (const float4*)(Wc + c * 128);
#pragma unroll 8
        for (int k = 0; k < 32; ++k) {
            float4 a = wh4[k], d = wc4[k];
            float z0 = zs[4 * k], z1 = zs[4 * k + 1], z2 = zs[4 * k + 2], z3 = zs[4 * k + 3];
            sh += a.x * z0 + a.y * z1 + a.z * z2 + a.w * z3;
            sc += d.x * z0 + d.y * z1 + d.z * z2 + d.w * z3;
        }
        if (c < 256) { g_h0all[b * 256 + c] = sh;       g_c0[b * 256 + c] = sc; }
        else         { g_h1all[b * 256 + c - 256] = sh; g_c1[b * 256 + c - 256] = sc; }
    }
    {
        int c = tid;
        float s = bx[c];
        const float4* w4 = (const float4*)(Wx + c * 128);
#pragma unroll 8
        for (int k = 0; k < 32; ++k) {
            float4 a = w4[k];
            s += a.x * zs[4 * k] + a.y * zs[4 * k + 1] + a.z * zs[4 * k + 2] + a.w * zs[4 * k + 3];
        }
        g_x0[b * 256 + c] = s;
    }
}

// ---------------------------------------------------------------------------
// Init kernel 2: gx0 = x0 @ W_ih0^T + b_ih0 + b_hh0 ; b1sum ; barrier reset
// ---------------------------------------------------------------------------
__global__ void __launch_bounds__(256) init_gx0(
    const float* __restrict__ Wih0, const float* __restrict__ bih0, const float* __restrict__ bhh0,
    const float* __restrict__ bih1, const float* __restrict__ bhh1)
{
    __shared__ float xs[256];
    const int b = blockIdx.x, tid = threadIdx.x;
    xs[tid] = g_x0[b * 256 + tid];
    __syncthreads();
#pragma unroll
    for (int q = 0; q < 4; ++q) {
        int c = (q << 8) + tid;
        float s = bih0[c] + bhh0[c];
        const float4* w4 = (const float4*)(Wih0 + c * 256);
#pragma unroll 8
        for (int k = 0; k < 64; ++k) {
            float4 a = w4[k];
            s += a.x * xs[4 * k] + a.y * xs[4 * k + 1] + a.z * xs[4 * k + 2] + a.w * xs[4 * k + 3];
        }
        g_gx0[b * 1024 + c] = s;
    }
    if (b == 0) {
#pragma unroll
        for (int q = 0; q < 4; ++q) { int c = (q << 8) + tid; g_b1sum[c] = bih1[c] + bhh1[c]; }
        if (tid == 0) { g_bar_arrive = 0; g_bar_release = 0; }
    }
}

// ---------------------------------------------------------------------------
// Persistent kernel: both LSTM layers, layer1 pipelined one round behind.
// 128 CTAs = 8 batch-tiles x 16 j-tiles. 513 rounds, grid barrier each round.
// ---------------------------------------------------------------------------
__global__ void __launch_bounds__(128, 1) lstm_kernel(
    const float* __restrict__ Whh0f,
    const float* __restrict__ Wih1f,
    const float* __restrict__ Whh1f)
{
    __shared__ u64 Hsm[2 * 544];    // 2 bufs x 32 rows x 17 u64
    __shared__ u64 Wsm[4 * 1088];   // 2 bufs x 2 weights x 64 rows x 17 u64

    const int tid = threadIdx.x;
    const int b0 = (blockIdx.x & 7) << 5;
    const int j0 = (blockIdx.x >> 3) << 4;
    const int tc = tid & 15;
    const int tb4 = (tid >> 4) << 2;
    const int jcol = j0 + tc;
    const unsigned hs_sa = (unsigned)__cvta_generic_to_shared(Hsm);
    const unsigned ws_sa = (unsigned)__cvta_generic_to_shared(Wsm);
    const u64* Wr0 = (const u64*)Whh0f;
    const u64* Wx1 = (const u64*)Wih1f;
    const u64* Wr1 = (const u64*)Whh1f;

    // Sequence-invariant per-thread state in registers
    float gx[4][4], b1s[4], c0v[4], c1v[4];
#pragma unroll
    for (int i = 0; i < 4; ++i) {
        int b = b0 + tb4 + i;
#pragma unroll
        for (int g = 0; g < 4; ++g) gx[i][g] = g_gx0[b * 1024 + g * 256 + jcol];
        c0v[i] = g_c0[b * 256 + jcol];
        c1v[i] = g_c1[b * 256 + jcol];
    }
#pragma unroll
    for (int g = 0; g < 4; ++g) b1s[g] = g_b1sum[g * 256 + jcol];

#pragma unroll 1
    for (int r = 1; r <= 513; ++r) {
        u64 a0[4][4], a1[4][4];
#pragma unroll
        for (int i = 0; i < 4; ++i)
#pragma unroll
            for (int g = 0; g < 4; ++g) { a0[i][g] = 0ull; a1[i][g] = 0ull; }

        // Pass A: H = h0 slot r-1 feeds BOTH layer0 recurrent (Whh0 -> a0)
        // and layer1 input (Wih1 -> a1). Run every round (edges waste one acc).
        gemm_run(2, a0, a1, (const u64*)(g_h0all + (unsigned)(r - 1) * 65536u),
                 Wr0, Wx1, Hsm, Wsm, hs_sa, ws_sa, b0, j0, tid);

        // Pass B: layer1 recurrent, H = h1 slot r-2 (valid for r >= 2)
        if (r >= 2)
            gemm_run(1, a1, a1, (const u64*)(g_h1all + (unsigned)(r - 2) * 65536u),
                     Wr1, Wr1, Hsm, Wsm, hs_sa, ws_sa, b0, j0, tid);

        if (r <= 512) {   // layer0 pointwise, write h0 slot r
            float* dst = g_h0all + (unsigned)r * 65536u;
#pragma unroll
            for (int i = 0; i < 4; ++i) {
                float p0 = sum2(a0[i][0]) + gx[i][0];
                float p1 = sum2(a0[i][1]) + gx[i][1];
                float p2 = sum2(a0[i][2]) + gx[i][2];
                float p3 = sum2(a0[i][3]) + gx[i][3];
                float ig = sigf(p0), fg = sigf(p1), gg = tanhfast(p2), og = sigf(p3);
                c0v[i] = fg * c0v[i] + ig * gg;
                dst[(b0 + tb4 + i) * 256 + jcol] = og * tanhfast(c0v[i]);
            }
        }
        if (r >= 2) {     // layer1 pointwise (step r-2), write h1 slot r-1
            float* dst = g_h1all + (unsigned)(r - 1) * 65536u;
#pragma unroll
            for (int i = 0; i < 4; ++i) {
                float p0 = sum2(a1[i][0]) + b1s[0];
                float p1 = sum2(a1[i][1]) + b1s[1];
                float p2 = sum2(a1[i][2]) + b1s[2];
                float p3 = sum2(a1[i][3]) + b1s[3];
                float ig = sigf(p0), fg = sigf(p1), gg = tanhfast(p2), og = sigf(p3);
                c1v[i] = fg * c1v[i] + ig * gg;
                dst[(b0 + tb4 + i) * 256 + jcol] = og * tanhfast(c1v[i]);
            }
        }
        grid_sync((unsigned)r);
    }
}

// ---------------------------------------------------------------------------
// Output projection: out[b,s,:64] = h2[b,s,:] @ Wout^T + bout
// Block: 256 threads, 32 (b,s) rows. Wout cached in smem (pitch 257 ->
// conflict-free scalar reads); h rows broadcast within warp.
// ---------------------------------------------------------------------------
__global__ void __launch_bounds__(256) proj_kernel(
    const float* __restrict__ Wout, const float* __restrict__ bout,
    float* __restrict__ out)
{
    extern __shared__ float sm[];
    float* ws = sm;              // [64][257]
    float* hsr = sm + 64 * 257;  // [32][257]
    const int tid = threadIdx.x;
    const int lin0 = blockIdx.x * 32;

    for (int i = tid; i < 64 * 64; i += 256) {          // load Wout (float4)
        int row = i >> 6, k4 = i & 63;
        float4 v = ((const float4*)(Wout + row * 256))[k4];
        float* d = ws + row * 257 + k4 * 4;
        d[0] = v.x; d[1] = v.y; d[2] = v.z; d[3] = v.w;
    }
    for (int i = tid; i < 32 * 64; i += 256) {          // load 32 h2 rows
        int rr = i >> 6, k4 = i & 63;
        int lin = lin0 + rr, b = lin >> 9, s = lin & 511;
        float4 v = ((const float4*)(g_h1all + (unsigned)(s + 1) * 65536u + b * 256))[k4];
        float* d = hsr + rr * 257 + k4 * 4;
        d[0] = v.x; d[1] = v.y; d[2] = v.z; d[3] = v.w;
    }
    __syncthreads();

    const int o = tid & 63, rg = tid >> 6;  // 4 row-groups x 8 rows
    float acc[8];
    float bb = bout[o];
#pragma unroll
    for (int ri = 0; ri < 8; ++ri) acc[ri] = bb;
    const float* wrow = ws + o * 257;
    const float* hbase = hsr + (rg * 8) * 257;
#pragma unroll 4
    for (int k = 0; k < 256; ++k) {
        float wv = wrow[k];
#pragma unroll
        for (int ri = 0; ri < 8; ++ri) acc[ri] += hbase[ri * 257 + k] * wv;
    }
#pragma unroll
    for (int ri = 0; ri < 8; ++ri) {
        int lin = lin0 + rg * 8 + ri;
        out[(unsigned)lin * 64u + o] = acc[ri];
    }
}

// ---------------------------------------------------------------------------
// kernel_launch
// ---------------------------------------------------------------------------
extern "C" void kernel_launch(void* const* d_in, const int* in_sizes, int n_in,
                              void* d_out, int out_size)
{
    const float* z    = (const float*)d_in[0];
    const float* fhw  = (const float*)d_in[1];
    const float* fhb  = (const float*)d_in[2];
    const float* fcw  = (const float*)d_in[3];
    const float* fcb  = (const float*)d_in[4];
    const float* fiw  = (const float*)d_in[5];
    const float* fib  = (const float*)d_in[6];
    const float* Wih0 = (const float*)d_in[7];
    const float* Whh0 = (const float*)d_in[8];
    const float* bih0 = (const float*)d_in[9];
    const float* bhh0 = (const float*)d_in[10];
    const float* Wih1 = (const float*)d_in[11];
    const float* Whh1 = (const float*)d_in[12];
    const float* bih1 = (const float*)d_in[13];
    const float* bhh1 = (const float*)d_in[14];
    const float* Wout = (const float*)d_in[15];
    const float* bout = (const float*)d_in[16];
    float* out = (float*)d_out;

    cudaFuncSetAttribute(proj_kernel, cudaFuncAttributeMaxDynamicSharedMemorySize, 98688);

    init_states<<<256, 256>>>(z, fhw, fhb, fcw, fcb, fiw, fib);
    init_gx0<<<256, 256>>>(Wih0, bih0, bhh0, bih1, bhh1);
    lstm_kernel<<<128, 128>>>(Whh0, Wih1, Whh1);
    proj_kernel<<<4096, 256, 98688>>>(Wout, bout, out);
}

// round 6
// speedup vs baseline: 1.0794x; 1.0794x over previous
#include <cuda_runtime.h>
#include <math.h>

typedef unsigned long long u64;

// ---------------------------------------------------------------------------
// Device-global scratch (allocation-free contract: module globals only)
// Hidden-state rings are slot-major [slot][B][H]; slot 0 = initial state,
// slot s = output of step s. Round-unique addresses -> no stale-L1 hazard.
// ---------------------------------------------------------------------------
__device__ __align__(256) float g_h0all[513 * 256 * 256];  // layer0 h ring (~128MB)
__device__ __align__(256) float g_h1all[513 * 256 * 256];  // layer1 h ring (~128MB)
__device__ __align__(256) float g_c0[256 * 256];
__device__ __align__(256) float g_c1[256 * 256];
__device__ __align__(256) float g_x0[256 * 256];
__device__ __align__(256) float g_gx0[256 * 1024];         // x proj + b_ih0 + b_hh0
__device__ __align__(256) float g_b1sum[1024];             // b_ih1 + b_hh1
__device__ unsigned g_bar_arrive;
__device__ volatile unsigned g_bar_release;

// ---------------------------------------------------------------------------
// PTX helpers
// ---------------------------------------------------------------------------
#define CPA16(s, g) asm volatile("cp.async.ca.shared.global [%0], [%1], 16;" :: "r"(s), "l"(g))
#define CPCOMMIT()  asm volatile("cp.async.commit_group;")
#define CPWAIT0()   asm volatile("cp.async.wait_group 0;")
#define FMA2(d, a, b) asm("fma.rn.f32x2 %0, %1, %2, %0;" : "+l"(d) : "l"(a), "l"(b))

__device__ __forceinline__ float sum2(u64 v) {
    float lo, hi;
    asm("mov.b64 {%0,%1}, %2;" : "=f"(lo), "=f"(hi) : "l"(v));
    return lo + hi;
}
__device__ __forceinline__ float sigf(float x) {
    x = fminf(fmaxf(x, -30.f), 30.f);
    return 1.f / (1.f + __expf(-x));
}
__device__ __forceinline__ float tanhfast(float x) {
    x = fminf(fmaxf(x, -15.f), 15.f);
    float e = __expf(2.f * x);
    return (e - 1.f) / (e + 1.f);
}

// Software grid barrier (128 CTAs co-resident; round 1-based; counters reset
// by init_gx0 each launch).
__device__ __forceinline__ void grid_sync(unsigned round) {
    __syncthreads();
    if (threadIdx.x == 0) {
        __threadfence();
        unsigned old = atomicAdd(&g_bar_arrive, 1u);
        if (old + 1u == round * gridDim.x) {
            g_bar_release = round;
            __threadfence();
        } else {
            while (g_bar_release < round) __nanosleep(16);
            __threadfence();
        }
    }
    __syncthreads();
}

// ---------------------------------------------------------------------------
// Flat 32 KB H-tile copy: global rows [b0, b0+32) x 256 floats are contiguous.
// 8 x 16B chunks per thread, fully coalesced.
// ---------------------------------------------------------------------------
__device__ __forceinline__ void load_H(unsigned h_sa, const char* Hg, int tid) {
#pragma unroll
    for (int q = 0; q < 8; ++q) {
        unsigned off = (unsigned)(tid + (q << 8)) * 16u;
        CPA16(h_sa + off, Hg + off);
    }
    CPCOMMIT();
}

// Pass A: dual-weight GEMM over this thread's K-half (64 u64-k).
// a0 += Whh0 * h ; a1 += Wih1 * h
__device__ __forceinline__ void passA(
    u64 (&a0)[4][4], u64 (&a1)[4][4],
    const u64* __restrict__ Hbuf, const u64* __restrict__ W0s, const u64* __restrict__ W1s,
    int kbase, int tb4, int tc)
{
#pragma unroll 4
    for (int kk = 0; kk < 64; ++kk) {
        int k = kbase + kk;
        u64 hv[4];
#pragma unroll
        for (int i = 0; i < 4; ++i) hv[i] = Hbuf[(tb4 + i) * 128 + k];
        u64 wv[4];
#pragma unroll
        for (int g = 0; g < 4; ++g) wv[g] = W0s[k * 64 + g * 16 + tc];
#pragma unroll
        for (int i = 0; i < 4; ++i)
#pragma unroll
            for (int g = 0; g < 4; ++g) FMA2(a0[i][g], hv[i], wv[g]);
#pragma unroll
        for (int g = 0; g < 4; ++g) wv[g] = W1s[k * 64 + g * 16 + tc];
#pragma unroll
        for (int i = 0; i < 4; ++i)
#pragma unroll
            for (int g = 0; g < 4; ++g) FMA2(a1[i][g], hv[i], wv[g]);
    }
}

// Pass B: single-weight GEMM. a1 += Whh1 * h
__device__ __forceinline__ void passB(
    u64 (&a1)[4][4],
    const u64* __restrict__ Hbuf, const u64* __restrict__ W2s,
    int kbase, int tb4, int tc)
{
#pragma unroll 8
    for (int kk = 0; kk < 64; ++kk) {
        int k = kbase + kk;
        u64 hv[4];
#pragma unroll
        for (int i = 0; i < 4; ++i) hv[i] = Hbuf[(tb4 + i) * 128 + k];
        u64 wv[4];
#pragma unroll
        for (int g = 0; g < 4; ++g) wv[g] = W2s[k * 64 + g * 16 + tc];
#pragma unroll
        for (int i = 0; i < 4; ++i)
#pragma unroll
            for (int g = 0; g < 4; ++g) FMA2(a1[i][g], hv[i], wv[g]);
    }
}

// ---------------------------------------------------------------------------
// Init kernel 1: initial hidden/cell states + x0 (z-projections)
// ---------------------------------------------------------------------------
__global__ void __launch_bounds__(256) init_states(
    const float* __restrict__ z,
    const float* __restrict__ Wh, const float* __restrict__ bh,
    const float* __restrict__ Wc, const float* __restrict__ bc,
    const float* __restrict__ Wx, const float* __restrict__ bx)
{
    __shared__ float zs[128];
    const int b = blockIdx.x, tid = threadIdx.x;
    if (tid < 128) zs[tid] = z[b * 128 + tid];
    __syncthreads();
#pragma unroll
    for (int rep = 0; rep < 2; ++rep) {
        int c = tid + (rep << 8);
        float sh = bh[c], sc = bc[c];
        const float4* wh4 = (const float4*)(Wh + c * 128);
        const float4* wc4 = (const float4*)(Wc + c * 128);
#pragma unroll 8
        for (int k = 0; k < 32; ++k) {
            float4 a = wh4[k], d = wc4[k];
            float z0 = zs[4 * k], z1 = zs[4 * k + 1], z2 = zs[4 * k + 2], z3 = zs[4 * k + 3];
            sh += a.x * z0 + a.y * z1 + a.z * z2 + a.w * z3;
            sc += d.x * z0 + d.y * z1 + d.z * z2 + d.w * z3;
        }
        if (c < 256) { g_h0all[b * 256 + c] = sh;       g_c0[b * 256 + c] = sc; }
        else         { g_h1all[b * 256 + c - 256] = sh; g_c1[b * 256 + c - 256] = sc; }
    }
    {
        int c = tid;
        float s = bx[c];
        const float4* w4 = (const float4*)(Wx + c * 128);
#pragma unroll 8
        for (int k = 0; k < 32; ++k) {
            float4 a = w4[k];
            s += a.x * zs[4 * k] + a.y * zs[4 * k + 1] + a.z * zs[4 * k + 2] + a.w * zs[4 * k + 3];
        }
        g_x0[b * 256 + c] = s;
    }
}

// ---------------------------------------------------------------------------
// Init kernel 2: gx0 = x0 @ W_ih0^T + b_ih0 + b_hh0 ; b1sum ; barrier reset
// ---------------------------------------------------------------------------
__global__ void __launch_bounds__(256) init_gx0(
    const float* __restrict__ Wih0, const float* __restrict__ bih0, const float* __restrict__ bhh0,
    const float* __restrict__ bih1, const float* __restrict__ bhh1)
{
    __shared__ float xs[256];
    const int b = blockIdx.x, tid = threadIdx.x;
    xs[tid] = g_x0[b * 256 + tid];
    __syncthreads();
#pragma unroll
    for (int q = 0; q < 4; ++q) {
        int c = (q << 8) + tid;
        float s = bih0[c] + bhh0[c];
        const float4* w4 = (const float4*)(Wih0 + c * 256);
#pragma unroll 8
        for (int k = 0; k < 64; ++k) {
            float4 a = w4[k];
            s += a.x * xs[4 * k] + a.y * xs[4 * k + 1] + a.z * xs[4 * k + 2] + a.w * xs[4 * k + 3];
        }
        g_gx0[b * 1024 + c] = s;
    }
    if (b == 0) {
#pragma unroll
        for (int q = 0; q < 4; ++q) { int c = (q << 8) + tid; g_b1sum[c] = bih1[c] + bhh1[c]; }
        if (tid == 0) { g_bar_arrive = 0; g_bar_release = 0; }
    }
}

// ---------------------------------------------------------------------------
// Persistent LSTM kernel. 128 CTAs = 8 batch-tiles x 16 j-tiles, 256 threads.
// All 3 weight slices (192 KB) resident in smem for the whole sequence,
// kk-major [k][col] (col = gate*16 + tc) -> conflict-free wv reads, no pad.
// Threads K-split: half 0 -> K[0:128), half 1 -> K[128:256); reduced via smem.
// 513 rounds, layer1 pipelined one round behind layer0.
// ---------------------------------------------------------------------------
__global__ void __launch_bounds__(256, 1) lstm_kernel(
    const float* __restrict__ Whh0f,
    const float* __restrict__ Wih1f,
    const float* __restrict__ Whh1f)
{
    extern __shared__ u64 smd[];
    u64* W0s  = smd;            // [128][64] u64  (Whh0 slice)
    u64* W1s  = smd + 8192;     // Wih1 slice
    u64* W2s  = smd + 16384;    // Whh1 slice
    u64* Hbuf = smd + 24576;    // [32][128] u64 = 32 KB (also reduction area)
    float* Red = (float*)Hbuf;  // [128][33] floats

    const int tid  = threadIdx.x;
    const int half = tid >> 7;
    const int t    = tid & 127;
    const int tc   = t & 15;
    const int tb4  = (t >> 4) << 2;
    const int b0   = (blockIdx.x & 7) << 5;
    const int j0   = (blockIdx.x >> 3) << 4;
    const int jcol = j0 + tc;
    const int kbase = half << 6;
    const unsigned h_sa = (unsigned)__cvta_generic_to_shared(Hbuf);

    // One-time weight preload into smem, transposed to kk-major.
    {
        const u64* srcs[3] = { (const u64*)Whh0f, (const u64*)Wih1f, (const u64*)Whh1f };
        u64* dsts[3] = { W0s, W1s, W2s };
#pragma unroll 1
        for (int m = 0; m < 3; ++m) {
            const u64* src = srcs[m];
            u64* dst = dsts[m];
            for (int idx = tid; idx < 8192; idx += 256) {
                int k = idx >> 6, col = idx & 63;
                int grow = ((col >> 4) << 8) + j0 + (col & 15);   // gate*256 + j
                dst[idx] = src[(unsigned)grow * 128u + k];
            }
        }
    }

    // Sequence-invariant per-thread state (consumed by half 0 only)
    float gx[4][4], b1s[4], c0v[4], c1v[4];
#pragma unroll
    for (int i = 0; i < 4; ++i) {
        int b = b0 + tb4 + i;
#pragma unroll
        for (int g = 0; g < 4; ++g) gx[i][g] = g_gx0[b * 1024 + g * 256 + jcol];
        c0v[i] = g_c0[b * 256 + jcol];
        c1v[i] = g_c1[b * 256 + jcol];
    }
#pragma unroll
    for (int g = 0; g < 4; ++g) b1s[g] = g_b1sum[g * 256 + jcol];
    __syncthreads();

#pragma unroll 1
    for (int r = 1; r <= 513; ++r) {
        u64 a0[4][4], a1[4][4];
#pragma unroll
        for (int i = 0; i < 4; ++i)
#pragma unroll
            for (int g = 0; g < 4; ++g) { a0[i][g] = 0ull; a1[i][g] = 0ull; }

        // Pass A: h0[r-1] feeds layer0 recurrent (->a0) and layer1 input (->a1)
        load_H(h_sa, (const char*)(g_h0all + (size_t)(r - 1) * 65536u + b0 * 256), tid);
        CPWAIT0();
        __syncthreads();
        passA(a0, a1, Hbuf, W0s, W1s, kbase, tb4, tc);
        __syncthreads();            // done reading Hbuf

        // Pass B: layer1 recurrent on h1[r-2] (valid r >= 2)
        if (r >= 2) {
            load_H(h_sa, (const char*)(g_h1all + (size_t)(r - 2) * 65536u + b0 * 256), tid);
            CPWAIT0();
            __syncthreads();
            passB(a1, Hbuf, W2s, kbase, tb4, tc);
            __syncthreads();        // done reading Hbuf before reduction reuse
        }

        // K-split reduction: half 1 publishes f32 partial sums
        if (half) {
#pragma unroll
            for (int i = 0; i < 4; ++i)
#pragma unroll
                for (int g = 0; g < 4; ++g) {
                    Red[t * 33 + (i * 4 + g)]      = sum2(a0[i][g]);
                    Red[t * 33 + 16 + (i * 4 + g)] = sum2(a1[i][g]);
                }
        }
        __syncthreads();

        if (!half) {
            if (r <= 512) {   // layer0 pointwise -> h0 slot r
                float* dst = g_h0all + (size_t)r * 65536u;
#pragma unroll
                for (int i = 0; i < 4; ++i) {
                    float p0 = sum2(a0[i][0]) + Red[t * 33 + (i * 4 + 0)] + gx[i][0];
                    float p1 = sum2(a0[i][1]) + Red[t * 33 + (i * 4 + 1)] + gx[i][1];
                    float p2 = sum2(a0[i][2]) + Red[t * 33 + (i * 4 + 2)] + gx[i][2];
                    float p3 = sum2(a0[i][3]) + Red[t * 33 + (i * 4 + 3)] + gx[i][3];
                    float ig = sigf(p0), fg = sigf(p1), gg = tanhfast(p2), og = sigf(p3);
                    c0v[i] = fg * c0v[i] + ig * gg;
                    dst[(b0 + tb4 + i) * 256 + jcol] = og * tanhfast(c0v[i]);
                }
            }
            if (r >= 2) {     // layer1 pointwise (step r-1) -> h1 slot r-1
                float* dst = g_h1all + (size_t)(r - 1) * 65536u;
#pragma unroll
                for (int i = 0; i < 4; ++i) {
                    float p0 = sum2(a1[i][0]) + Red[t * 33 + 16 + (i * 4 + 0)] + b1s[0];
                    float p1 = sum2(a1[i][1]) + Red[t * 33 + 16 + (i * 4 + 1)] + b1s[1];
                    float p2 = sum2(a1[i][2]) + Red[t * 33 + 16 + (i * 4 + 2)] + b1s[2];
                    float p3 = sum2(a1[i][3]) + Red[t * 33 + 16 + (i * 4 + 3)] + b1s[3];
                    float ig = sigf(p0), fg = sigf(p1), gg = tanhfast(p2), og = sigf(p3);
                    c1v[i] = fg * c1v[i] + ig * gg;
                    dst[(b0 + tb4 + i) * 256 + jcol] = og * tanhfast(c1v[i]);
                }
            }
        }
        grid_sync((unsigned)r);
    }
}

// ---------------------------------------------------------------------------
// Output projection: out[b,s,:64] = h2[b,s,:] @ Wout^T + bout
// ---------------------------------------------------------------------------
__global__ void __launch_bounds__(256) proj_kernel(
    const float* __restrict__ Wout, const float* __restrict__ bout,
    float* __restrict__ out)
{
    extern __shared__ float sm[];
    float* ws = sm;              // [64][257]
    float* hsr = sm + 64 * 257;  // [32][257]
    const int tid = threadIdx.x;
    const int lin0 = blockIdx.x * 32;

    for (int i = tid; i < 64 * 64; i += 256) {
        int row = i >> 6, k4 = i & 63;
        float4 v = ((const float4*)(Wout + row * 256))[k4];
        float* d = ws + row * 257 + k4 * 4;
        d[0] = v.x; d[1] = v.y; d[2] = v.z; d[3] = v.w;
    }
    for (int i = tid; i < 32 * 64; i += 256) {
        int rr = i >> 6, k4 = i & 63;
        int lin = lin0 + rr, b = lin >> 9, s = lin & 511;
        float4 v = ((const float4*)(g_h1all + (size_t)(s + 1) * 65536u + b * 256))[k4];
        float* d = hsr + rr * 257 + k4 * 4;
        d[0] = v.x; d[1] = v.y; d[2] = v.z; d[3] = v.w;
    }
    __syncthreads();

    const int o = tid & 63, rg = tid >> 6;
    float acc[8];
    float bb = bout[o];
#pragma unroll
    for (int ri = 0; ri < 8; ++ri) acc[ri] = bb;
    const float* wrow = ws + o * 257;
    const float* hbase = hsr + (rg * 8) * 257;
#pragma unroll 4
    for (int k = 0; k < 256; ++k) {
        float wv = wrow[k];
#pragma unroll
        for (int ri = 0; ri < 8; ++ri) acc[ri] += hbase[ri * 257 + k] * wv;
    }
#pragma unroll
    for (int ri = 0; ri < 8; ++ri) {
        int lin = lin0 + rg * 8 + ri;
        out[(unsigned)lin * 64u + o] = acc[ri];
    }
}

// ---------------------------------------------------------------------------
// kernel_launch
// ---------------------------------------------------------------------------
extern "C" void kernel_launch(void* const* d_in, const int* in_sizes, int n_in,
                              void* d_out, int out_size)
{
    const float* z    = (const float*)d_in[0];
    const float* fhw  = (const float*)d_in[1];
    const float* fhb  = (const float*)d_in[2];
    const float* fcw  = (const float*)d_in[3];
    const float* fcb  = (const float*)d_in[4];
    const float* fiw  = (const float*)d_in[5];
    const float* fib  = (const float*)d_in[6];
    const float* Wih0 = (const float*)d_in[7];
    const float* Whh0 = (const float*)d_in[8];
    const float* bih0 = (const float*)d_in[9];
    const float* bhh0 = (const float*)d_in[10];
    const float* Wih1 = (const float*)d_in[11];
    const float* Whh1 = (const float*)d_in[12];
    const float* bih1 = (const float*)d_in[13];
    const float* bhh1 = (const float*)d_in[14];
    const float* Wout = (const float*)d_in[15];
    const float* bout = (const float*)d_in[16];
    float* out = (float*)d_out;

    static int smem_set = 0;
    if (!smem_set) {
        cudaFuncSetAttribute(lstm_kernel, cudaFuncAttributeMaxDynamicSharedMemorySize, 229376);
        cudaFuncSetAttribute(proj_kernel, cudaFuncAttributeMaxDynamicSharedMemorySize, 98688);
        smem_set = 1;
    }

    init_states<<<256, 256>>>(z, fhw, fhb, fcw, fcb, fiw, fib);
    init_gx0<<<256, 256>>>(Wih0, bih0, bhh0, bih1, bhh1);
    lstm_kernel<<<128, 256, 229376>>>(Whh0, Wih1, Whh1);
    proj_kernel<<<4096, 256, 98688>>>(Wout, bout, out);
}

// round 8
// speedup vs baseline: 1.3346x; 1.2364x over previous
#include <cuda_runtime.h>
#include <cuda_bf16.h>
#include <math.h>
#include <stdint.h>

typedef unsigned long long u64;
typedef unsigned int u32;

// ---------------------------------------------------------------------------
// Device-global scratch. Hidden rings split bf16 (hi+lo), slot-major
// [slot][B][H]; slot 0 = initial state, slot s = output of step s.
// Slot-unique addresses -> no stale-L1 hazard across the software barrier.
// ---------------------------------------------------------------------------
#define RING_ELEMS (513 * 256 * 256)
__device__ __align__(256) __nv_bfloat16 g_h0hi[RING_ELEMS];
__device__ __align__(256) __nv_bfloat16 g_h0lo[RING_ELEMS];
__device__ __align__(256) __nv_bfloat16 g_h1hi[RING_ELEMS];
__device__ __align__(256) __nv_bfloat16 g_h1lo[RING_ELEMS];
__device__ __align__(256) float g_c0[256 * 256];
__device__ __align__(256) float g_c1[256 * 256];
__device__ __align__(256) float g_x0[256 * 256];
__device__ __align__(256) float g_gx0[256 * 1024];   // x-proj + b_ih0 + b_hh0
__device__ __align__(256) float g_b1sum[1024];       // b_ih1 + b_hh1
__device__ unsigned g_bar_arrive;
__device__ volatile unsigned g_bar_release;

// ---------------------------------------------------------------------------
// PTX helpers (all sm_80-level: compile for compute_103)
// ---------------------------------------------------------------------------
#define CPA16(s, g) asm volatile("cp.async.ca.shared.global [%0], [%1], 16;" :: "r"(s), "l"(g))
#define CPCOMMIT()  asm volatile("cp.async.commit_group;")
#define CPWAIT1()   asm volatile("cp.async.wait_group 1;")
#define CPWAIT0()   asm volatile("cp.async.wait_group 0;")

#define LDSM4(r, addr) \
    asm volatile("ldmatrix.sync.aligned.m8n8.x4.shared.b16 {%0,%1,%2,%3}, [%4];" \
        : "=r"((r)[0]), "=r"((r)[1]), "=r"((r)[2]), "=r"((r)[3]) : "r"(addr))

#define LDS64(b, addr) \
    asm volatile("ld.shared.v2.u32 {%0,%1}, [%2];" \
        : "=r"((b)[0]), "=r"((b)[1]) : "r"(addr))

#define MMA(d, a, b) \
    asm volatile("mma.sync.aligned.m16n8k16.row.col.f32.bf16.bf16.f32 " \
        "{%0,%1,%2,%3}, {%4,%5,%6,%7}, {%8,%9}, {%0,%1,%2,%3};" \
        : "+f"((d)[0]), "+f"((d)[1]), "+f"((d)[2]), "+f"((d)[3]) \
        : "r"((a)[0]), "r"((a)[1]), "r"((a)[2]), "r"((a)[3]), "r"((b)[0]), "r"((b)[1]))

__device__ __forceinline__ float sigf(float x) {
    x = fminf(fmaxf(x, -30.f), 30.f);
    return 1.f / (1.f + __expf(-x));
}
__device__ __forceinline__ float tanhfast(float x) {
    x = fminf(fmaxf(x, -15.f), 15.f);
    float e = __expf(2.f * x);
    return (e - 1.f) / (e + 1.f);
}

__device__ __forceinline__ void grid_sync(unsigned round) {
    __syncthreads();
    if (threadIdx.x == 0) {
        __threadfence();
        unsigned old = atomicAdd(&g_bar_arrive, 1u);
        if (old + 1u == round * gridDim.x) {
            g_bar_release = round;
            __threadfence();
        } else {
            while (g_bar_release < round) __nanosleep(16);
            __threadfence();
        }
    }
    __syncthreads();
}

// ---------------------------------------------------------------------------
// Weight fragment address: element (n, k) of an N x 256 slice, fragment order
// for mma B (col-major 16x8 per (ntile, kstep) block of 256B).
// ---------------------------------------------------------------------------
__device__ __forceinline__ int wfrag_off(int n, int k) {
    int nt = n >> 3, s = k >> 4, kl = k & 15;
    int lw = ((n & 7) << 2) | ((kl & 7) >> 1);
    return (((nt * 16 + s) * 32 + lw) << 3) + ((kl >> 3) << 2) + ((kl & 1) << 1);
}

// ---------------------------------------------------------------------------
// Init kernel 1: initial hidden/cell states (ring slot 0, split bf16) + x0
// ---------------------------------------------------------------------------
__global__ void __launch_bounds__(256) init_states(
    const float* __restrict__ z,
    const float* __restrict__ Wh, const float* __restrict__ bh,
    const float* __restrict__ Wc, const float* __restrict__ bc,
    const float* __restrict__ Wx, const float* __restrict__ bx)
{
    __shared__ float zs[128];
    const int b = blockIdx.x, tid = threadIdx.x;
    if (tid < 128) zs[tid] = z[b * 128 + tid];
    __syncthreads();
#pragma unroll
    for (int rep = 0; rep < 2; ++rep) {
        int c = tid + (rep << 8);
        float sh = bh[c], sc = bc[c];
        const float4* wh4 = (const float4*)(Wh + c * 128);
        const float4* wc4 = (const float4*)(Wc + c * 128);
#pragma unroll 8
        for (int k = 0; k < 32; ++k) {
            float4 a = wh4[k], d = wc4[k];
            float z0 = zs[4 * k], z1 = zs[4 * k + 1], z2 = zs[4 * k + 2], z3 = zs[4 * k + 3];
            sh += a.x * z0 + a.y * z1 + a.z * z2 + a.w * z3;
            sc += d.x * z0 + d.y * z1 + d.z * z2 + d.w * z3;
        }
        __nv_bfloat16 hi = __float2bfloat16(sh);
        __nv_bfloat16 lo = __float2bfloat16(sh - __bfloat162float(hi));
        if (c < 256) {
            g_h0hi[b * 256 + c] = hi; g_h0lo[b * 256 + c] = lo;
            g_c0[b * 256 + c] = sc;
        } else {
            g_h1hi[b * 256 + c - 256] = hi; g_h1lo[b * 256 + c - 256] = lo;
            g_c1[b * 256 + c - 256] = sc;
        }
    }
    {
        int c = tid;
        float s = bx[c];
        const float4* w4 = (const float4*)(Wx + c * 128);
#pragma unroll 8
        for (int k = 0; k < 32; ++k) {
            float4 a = w4[k];
            s += a.x * zs[4 * k] + a.y * zs[4 * k + 1] + a.z * zs[4 * k + 2] + a.w * zs[4 * k + 3];
        }
        g_x0[b * 256 + c] = s;
    }
}

// ---------------------------------------------------------------------------
// Init kernel 2: gx0 = x0 @ W_ih0^T + b_ih0 + b_hh0 ; b1sum ; barrier reset
// ---------------------------------------------------------------------------
__global__ void __launch_bounds__(256) init_gx0(
    const float* __restrict__ Wih0, const float* __restrict__ bih0, const float* __restrict__ bhh0,
    const float* __restrict__ bih1, const float* __restrict__ bhh1)
{
    __shared__ float xs[256];
    const int b = blockIdx.x, tid = threadIdx.x;
    xs[tid] = g_x0[b * 256 + tid];
    __syncthreads();
#pragma unroll
    for (int q = 0; q < 4; ++q) {
        int c = (q << 8) + tid;
        float s = bih0[c] + bhh0[c];
        const float4* w4 = (const float4*)(Wih0 + c * 256);
#pragma unroll 8
        for (int k = 0; k < 64; ++k) {
            float4 a = w4[k];
            s += a.x * xs[4 * k] + a.y * xs[4 * k + 1] + a.z * xs[4 * k + 2] + a.w * xs[4 * k + 3];
        }
        g_gx0[b * 1024 + c] = s;
    }
    if (b == 0) {
#pragma unroll
        for (int q = 0; q < 4; ++q) { int c = (q << 8) + tid; g_b1sum[c] = bih1[c] + bhh1[c]; }
        if (tid == 0) { g_bar_arrive = 0; g_bar_release = 0; }
    }
}

// ---------------------------------------------------------------------------
// Persistent mma.sync LSTM kernel, 96 CTAs x 128 threads (4 warps).
//   CTA 0..31 : layer0. m = lidx&1 (batch half), j0 = (lidx>>1)*16.
//               Tile M=128 x N=64 (col = gate*16 + jj), K=256, 3-term bf16.
//   CTA 32..95: layer1. m = lidx&1, j0 = (lidx>>1)*8.
//               Tile M=128 x N=32 (col = gate*8 + jj), two phases into one acc.
// Warp w owns rows w*32..w*32+31 (2 m16 tiles). A from ring via cp.async +
// XOR-swizzled ldmatrix; W fragments resident in smem (plain LDS.64).
// ---------------------------------------------------------------------------
struct L0Acc { float a[2][8][4]; };
struct L1Acc { float a[2][4][4]; };

__device__ __forceinline__ void stage_half(
    u32 Ah_sa, u32 Al_sa, const char* sh, const char* sl, int tid, int half)
{
#pragma unroll
    for (int it = 0; it < 16; ++it) {
        int idq = tid + (it << 7);          // 0..2047
        int row = idq >> 4;
        int c = (idq & 15) + half * 16;     // 16B chunk within 512B row
        u32 d = (u32)row * 512u + (u32)((c ^ (row & 7)) << 4);
        u32 so = (u32)row * 512u + (u32)(c << 4);
        CPA16(Ah_sa + d, sh + so);
        CPA16(Al_sa + d, sl + so);
    }
    CPCOMMIT();
}

__device__ __forceinline__ void compute8_l0(
    L0Acc& A, int s0, u32 Ah_sa, u32 Al_sa, u32 Wf_sa,
    u32 rb0, u32 rb1, u32 chs, u32 rsw, u32 bl8)
{
#pragma unroll 1
    for (int ss = 0; ss < 8; ++ss) {
        int s = s0 + ss;
        u32 so = (u32)((((u32)(s << 1) + chs) ^ rsw) << 4);
        u32 ah0[4], ah1[4], al0[4], al1[4];
        LDSM4(ah0, Ah_sa + rb0 + so); LDSM4(ah1, Ah_sa + rb1 + so);
        LDSM4(al0, Al_sa + rb0 + so); LDSM4(al1, Al_sa + rb1 + so);
#pragma unroll
        for (int nt = 0; nt < 8; ++nt) {
            u32 bh[2], bl[2];
            u32 ba = Wf_sa + (u32)((nt * 16 + s) << 8) + bl8;
            LDS64(bh, ba); LDS64(bl, ba + 32768u);
            MMA(A.a[0][nt], ah0, bh); MMA(A.a[1][nt], ah1, bh);
            MMA(A.a[0][nt], ah0, bl); MMA(A.a[1][nt], ah1, bl);
            MMA(A.a[0][nt], al0, bh); MMA(A.a[1][nt], al1, bh);
        }
    }
}

__device__ __forceinline__ void compute8_l1(
    L1Acc& A, int s0, u32 Ah_sa, u32 Al_sa, u32 woh, u32 wol,
    u32 rb0, u32 rb1, u32 chs, u32 rsw, u32 bl8)
{
#pragma unroll 1
    for (int ss = 0; ss < 8; ++ss) {
        int s = s0 + ss;
        u32 so = (u32)((((u32)(s << 1) + chs) ^ rsw) << 4);
        u32 ah0[4], ah1[4], al0[4], al1[4];
        LDSM4(ah0, Ah_sa + rb0 + so); LDSM4(ah1, Ah_sa + rb1 + so);
        LDSM4(al0, Al_sa + rb0 + so); LDSM4(al1, Al_sa + rb1 + so);
#pragma unroll
        for (int nt = 0; nt < 4; ++nt) {
            u32 bh[2], bl[2];
            u32 boff = (u32)((nt * 16 + s) << 8) + bl8;
            LDS64(bh, woh + boff); LDS64(bl, wol + boff);
            MMA(A.a[0][nt], ah0, bh); MMA(A.a[1][nt], ah1, bh);
            MMA(A.a[0][nt], ah0, bl); MMA(A.a[1][nt], ah1, bl);
            MMA(A.a[0][nt], al0, bh); MMA(A.a[1][nt], al1, bh);
        }
    }
}

__global__ void __launch_bounds__(128, 1) lstm_kernel(
    const float* __restrict__ Whh0f,
    const float* __restrict__ Wih1f,
    const float* __restrict__ Whh1f)
{
    extern __shared__ char smem_raw[];
    char* sm = smem_raw;
    const u32 smb = (u32)__cvta_generic_to_shared(sm);
    const u32 Ah_sa = smb;                 // A hi: 128 x 512B = 64 KB
    const u32 Al_sa = smb + 65536u;        // A lo: 64 KB
    const u32 Wf_sa = smb + 131072u;       // W fragments: 64 KB
    char* Wf = sm + 131072;
    float* gxs = (float*)(sm + 196608);    // L0 only: 64 x 128 f32 = 32 KB

    const int tid = threadIdx.x;
    const int lane = tid & 31, w = tid >> 5;
    const bool is_l0 = blockIdx.x < 32;
    const int lidx = is_l0 ? (int)blockIdx.x : (int)blockIdx.x - 32;
    const int m = lidx & 1;
    const int j0 = is_l0 ? ((lidx >> 1) << 4) : ((lidx >> 1) << 3);
    const int q = lane >> 2;
    const int c2 = (lane & 3) << 1;

    // ldmatrix per-thread address precompute
    const int rA = (lane & 7) + (((lane >> 3) & 1) << 3);
    const u32 chs = (u32)(lane >> 4);
    const u32 rsw = (u32)(lane & 7);
    const u32 rb0 = (u32)(w * 32 + rA) * 512u;
    const u32 rb1 = rb0 + 8192u;           // +16 rows
    const u32 bl8 = (u32)lane * 8u;

    // ---- one-time weight fragment staging (fp32 -> split bf16) ----
    if (is_l0) {
        for (int e = tid; e < 16384; e += 128) {
            int n = e >> 8, k = e & 255;
            int wr = (n >> 4) * 256 + j0 + (n & 15);   // n = gate*16 + jj
            float v = Whh0f[wr * 256 + k];
            __nv_bfloat16 hi = __float2bfloat16(v);
            __nv_bfloat16 lo = __float2bfloat16(v - __bfloat162float(hi));
            int off = wfrag_off(n, k);
            *(__nv_bfloat16*)(Wf + off) = hi;
            *(__nv_bfloat16*)(Wf + 32768 + off) = lo;
        }
    } else {
        for (int mm = 0; mm < 2; ++mm) {
            const float* src = mm ? Whh1f : Wih1f;
            char* dh = Wf + mm * 32768;
            for (int e = tid; e < 8192; e += 128) {
                int n = e >> 8, k = e & 255;
                int wr = (n >> 3) * 256 + j0 + (n & 7); // n = gate*8 + jj
                float v = src[wr * 256 + k];
                __nv_bfloat16 hi = __float2bfloat16(v);
                __nv_bfloat16 lo = __float2bfloat16(v - __bfloat162float(hi));
                int off = wfrag_off(n, k);
                *(__nv_bfloat16*)(dh + off) = hi;
                *(__nv_bfloat16*)(dh + 16384 + off) = lo;
            }
        }
    }

    // ---- sequence-invariant per-thread state ----
    float cval[16];
    float b1v[8];
    if (is_l0) {
#pragma unroll
        for (int mt = 0; mt < 2; ++mt)
#pragma unroll
            for (int rh = 0; rh < 2; ++rh) {
                int row = m * 128 + w * 32 + mt * 16 + rh * 8 + q;
#pragma unroll
                for (int nt = 0; nt < 8; ++nt) {
                    int g = nt >> 1;
#pragma unroll
                    for (int e = 0; e < 2; ++e) {
                        int j = j0 + (nt & 1) * 8 + c2 + e;
                        int i = (mt * 8 + nt) * 4 + rh * 2 + e;
                        gxs[i * 128 + tid] = g_gx0[row * 1024 + g * 256 + j];
                    }
                }
#pragma unroll
                for (int nth = 0; nth < 2; ++nth)
#pragma unroll
                    for (int e = 0; e < 2; ++e)
                        cval[mt * 8 + rh * 4 + nth * 2 + e] =
                            g_c0[row * 256 + j0 + nth * 8 + c2 + e];
            }
    } else {
#pragma unroll
        for (int mt = 0; mt < 2; ++mt)
#pragma unroll
            for (int rh = 0; rh < 2; ++rh) {
                int row = m * 128 + w * 32 + mt * 16 + rh * 8 + q;
#pragma unroll
                for (int e = 0; e < 2; ++e)
                    cval[mt * 4 + rh * 2 + e] = g_c1[row * 256 + j0 + c2 + e];
            }
#pragma unroll
        for (int g = 0; g < 4; ++g)
#pragma unroll
            for (int e = 0; e < 2; ++e)
                b1v[g * 2 + e] = g_b1sum[g * 256 + j0 + c2 + e];
    }
    __syncthreads();

    if (is_l0) {
        // =================== LAYER 0 ===================
#pragma unroll 1
        for (int r = 1; r <= 513; ++r) {
            if (r <= 512) {
                L0Acc A;
#pragma unroll
                for (int mt = 0; mt < 2; ++mt)
#pragma unroll
                    for (int nt = 0; nt < 8; ++nt)
#pragma unroll
                        for (int i = 0; i < 4; ++i) A.a[mt][nt][i] = 0.f;

                size_t rbase = (size_t)(r - 1) * 65536u + (size_t)m * 32768u;
                const char* sh = (const char*)(g_h0hi + rbase);
                const char* sl = (const char*)(g_h0lo + rbase);
                stage_half(Ah_sa, Al_sa, sh, sl, tid, 0);
                stage_half(Ah_sa, Al_sa, sh, sl, tid, 1);
                CPWAIT1(); __syncthreads();
                compute8_l0(A, 0, Ah_sa, Al_sa, Wf_sa, rb0, rb1, chs, rsw, bl8);
                CPWAIT0(); __syncthreads();
                compute8_l0(A, 8, Ah_sa, Al_sa, Wf_sa, rb0, rb1, chs, rsw, bl8);

                // epilogue -> h0 slot r
                size_t os = (size_t)r * 65536u;
#pragma unroll
                for (int mt = 0; mt < 2; ++mt)
#pragma unroll
                    for (int rh = 0; rh < 2; ++rh) {
                        int row = m * 128 + w * 32 + mt * 16 + rh * 8 + q;
#pragma unroll
                        for (int nth = 0; nth < 2; ++nth) {
                            float hvv[2];
#pragma unroll
                            for (int e = 0; e < 2; ++e) {
                                int ci = mt * 8 + rh * 4 + nth * 2 + e;
                                int ib = rh * 2 + e;
                                float pi = A.a[mt][0 + nth][ib] + gxs[((mt * 8 + 0 + nth) * 4 + ib) * 128 + tid];
                                float pf = A.a[mt][2 + nth][ib] + gxs[((mt * 8 + 2 + nth) * 4 + ib) * 128 + tid];
                                float pg = A.a[mt][4 + nth][ib] + gxs[((mt * 8 + 4 + nth) * 4 + ib) * 128 + tid];
                                float po = A.a[mt][6 + nth][ib] + gxs[((mt * 8 + 6 + nth) * 4 + ib) * 128 + tid];
                                float ig = sigf(pi), fg = sigf(pf), gg = tanhfast(pg), og = sigf(po);
                                cval[ci] = fg * cval[ci] + ig * gg;
                                hvv[e] = og * tanhfast(cval[ci]);
                            }
                            int col = j0 + nth * 8 + c2;
                            __nv_bfloat16 h0b = __float2bfloat16(hvv[0]);
                            __nv_bfloat16 h1b = __float2bfloat16(hvv[1]);
                            __nv_bfloat16 l0b = __float2bfloat16(hvv[0] - __bfloat162float(h0b));
                            __nv_bfloat16 l1b = __float2bfloat16(hvv[1] - __bfloat162float(h1b));
                            u32 ph = ((u32)__bfloat16_as_ushort(h1b) << 16) | (u32)__bfloat16_as_ushort(h0b);
                            u32 pl = ((u32)__bfloat16_as_ushort(l1b) << 16) | (u32)__bfloat16_as_ushort(l0b);
                            *(u32*)(g_h0hi + os + (size_t)row * 256 + col) = ph;
                            *(u32*)(g_h0lo + os + (size_t)row * 256 + col) = pl;
                        }
                    }
            }
            grid_sync((unsigned)r);
        }
    } else {
        // =================== LAYER 1 ===================
#pragma unroll 1
        for (int r = 1; r <= 513; ++r) {
            if (r >= 2) {
                L1Acc A;
#pragma unroll
                for (int mt = 0; mt < 2; ++mt)
#pragma unroll
                    for (int nt = 0; nt < 4; ++nt)
#pragma unroll
                        for (int i = 0; i < 4; ++i) A.a[mt][nt][i] = 0.f;

                // phase 0: h0[r-1] * Wih1
                {
                    size_t rbase = (size_t)(r - 1) * 65536u + (size_t)m * 32768u;
                    const char* sh = (const char*)(g_h0hi + rbase);
                    const char* sl = (const char*)(g_h0lo + rbase);
                    stage_half(Ah_sa, Al_sa, sh, sl, tid, 0);
                    stage_half(Ah_sa, Al_sa, sh, sl, tid, 1);
                    CPWAIT1(); __syncthreads();
                    compute8_l1(A, 0, Ah_sa, Al_sa, Wf_sa, Wf_sa + 16384u, rb0, rb1, chs, rsw, bl8);
                    CPWAIT0(); __syncthreads();
                    compute8_l1(A, 8, Ah_sa, Al_sa, Wf_sa, Wf_sa + 16384u, rb0, rb1, chs, rsw, bl8);
                }
                __syncthreads();   // all warps done reading A before restage
                // phase 1: h1[r-2] * Whh1
                {
                    size_t rbase = (size_t)(r - 2) * 65536u + (size_t)m * 32768u;
                    const char* sh = (const char*)(g_h1hi + rbase);
                    const char* sl = (const char*)(g_h1lo + rbase);
                    stage_half(Ah_sa, Al_sa, sh, sl, tid, 0);
                    stage_half(Ah_sa, Al_sa, sh, sl, tid, 1);
                    CPWAIT1(); __syncthreads();
                    compute8_l1(A, 0, Ah_sa, Al_sa, Wf_sa + 32768u, Wf_sa + 49152u, rb0, rb1, chs, rsw, bl8);
                    CPWAIT0(); __syncthreads();
                    compute8_l1(A, 8, Ah_sa, Al_sa, Wf_sa + 32768u, Wf_sa + 49152u, rb0, rb1, chs, rsw, bl8);
                }

                // epilogue -> h1 slot r-1
                size_t os = (size_t)(r - 1) * 65536u;
#pragma unroll
                for (int mt = 0; mt < 2; ++mt)
#pragma unroll
                    for (int rh = 0; rh < 2; ++rh) {
                        int row = m * 128 + w * 32 + mt * 16 + rh * 8 + q;
                        float hvv[2];
#pragma unroll
                        for (int e = 0; e < 2; ++e) {
                            int ci = mt * 4 + rh * 2 + e;
                            int ib = rh * 2 + e;
                            float pi = A.a[mt][0][ib] + b1v[0 + e];
                            float pf = A.a[mt][1][ib] + b1v[2 + e];
                            float pg = A.a[mt][2][ib] + b1v[4 + e];
                            float po = A.a[mt][3][ib] + b1v[6 + e];
                            float ig = sigf(pi), fg = sigf(pf), gg = tanhfast(pg), og = sigf(po);
                            cval[ci] = fg * cval[ci] + ig * gg;
                            hvv[e] = og * tanhfast(cval[ci]);
                        }
                        int col = j0 + c2;
                        __nv_bfloat16 h0b = __float2bfloat16(hvv[0]);
                        __nv_bfloat16 h1b = __float2bfloat16(hvv[1]);
                        __nv_bfloat16 l0b = __float2bfloat16(hvv[0] - __bfloat162float(h0b));
                        __nv_bfloat16 l1b = __float2bfloat16(hvv[1] - __bfloat162float(h1b));
                        u32 ph = ((u32)__bfloat16_as_ushort(h1b) << 16) | (u32)__bfloat16_as_ushort(h0b);
                        u32 pl = ((u32)__bfloat16_as_ushort(l1b) << 16) | (u32)__bfloat16_as_ushort(l0b);
                        *(u32*)(g_h1hi + os + (size_t)row * 256 + col) = ph;
                        *(u32*)(g_h1lo + os + (size_t)row * 256 + col) = pl;
                    }
            }
            grid_sync((unsigned)r);
        }
    }
}

// ---------------------------------------------------------------------------
// Output projection: out[b,s,:64] = (h1hi+h1lo)[b,s,:] @ Wout^T + bout
// ---------------------------------------------------------------------------
__global__ void __launch_bounds__(256) proj_kernel(
    const float* __restrict__ Wout, const float* __restrict__ bout,
    float* __restrict__ out)
{
    extern __shared__ float sm[];
    float* ws = sm;              // [64][257]
    float* hsr = sm + 64 * 257;  // [32][257]
    const int tid = threadIdx.x;
    const int lin0 = blockIdx.x * 32;

    for (int i = tid; i < 64 * 64; i += 256) {
        int row = i >> 6, k4 = i & 63;
        float4 v = ((const float4*)(Wout + row * 256))[k4];
        float* d = ws + row * 257 + k4 * 4;
        d[0] = v.x; d[1] = v.y; d[2] = v.z; d[3] = v.w;
    }
    for (int i = tid; i < 32 * 32; i += 256) {
        int rr = i >> 5, ch = i & 31;
        int lin = lin0 + rr, b = lin >> 9, s = lin & 511;
        size_t off = (size_t)(s + 1) * 65536u + (size_t)b * 256u + (size_t)ch * 8u;
        uint4 vh = *(const uint4*)(g_h1hi + off);
        uint4 vl = *(const uint4*)(g_h1lo + off);
        const __nv_bfloat16* ph = (const __nv_bfloat16*)&vh;
        const __nv_bfloat16* pl = (const __nv_bfloat16*)&vl;
        float* d = hsr + rr * 257 + ch * 8;
#pragma unroll
        for (int k = 0; k < 8; ++k)
            d[k] = __bfloat162float(ph[k]) + __bfloat162float(pl[k]);
    }
    __syncthreads();

    const int o = tid & 63, rg = tid >> 6;
    float acc[8];
    float bb = bout[o];
#pragma unroll
    for (int ri = 0; ri < 8; ++ri) acc[ri] = bb;
    const float* wrow = ws + o * 257;
    const float* hbase = hsr + (rg * 8) * 257;
#pragma unroll 4
    for (int k = 0; k < 256; ++k) {
        float wv = wrow[k];
#pragma unroll
        for (int ri = 0; ri < 8; ++ri) acc[ri] += hbase[ri * 257 + k] * wv;
    }
#pragma unroll
    for (int ri = 0; ri < 8; ++ri) {
        int lin = lin0 + rg * 8 + ri;
        out[(unsigned)lin * 64u + o] = acc[ri];
    }
}

// ---------------------------------------------------------------------------
// kernel_launch
// ---------------------------------------------------------------------------
extern "C" void kernel_launch(void* const* d_in, const int* in_sizes, int n_in,
                              void* d_out, int out_size)
{
    const float* z    = (const float*)d_in[0];
    const float* fhw  = (const float*)d_in[1];
    const float* fhb  = (const float*)d_in[2];
    const float* fcw  = (const float*)d_in[3];
    const float* fcb  = (const float*)d_in[4];
    const float* fiw  = (const float*)d_in[5];
    const float* fib  = (const float*)d_in[6];
    const float* Wih0 = (const float*)d_in[7];
    const float* Whh0 = (const float*)d_in[8];
    const float* bih0 = (const float*)d_in[9];
    const float* bhh0 = (const float*)d_in[10];
    const float* Wih1 = (const float*)d_in[11];
    const float* Whh1 = (const float*)d_in[12];
    const float* bih1 = (const float*)d_in[13];
    const float* bhh1 = (const float*)d_in[14];
    const float* Wout = (const float*)d_in[15];
    const float* bout = (const float*)d_in[16];
    float* out = (float*)d_out;

    static int smem_set = 0;
    if (!smem_set) {
        cudaFuncSetAttribute(lstm_kernel, cudaFuncAttributeMaxDynamicSharedMemorySize, 229376);
        cudaFuncSetAttribute(proj_kernel, cudaFuncAttributeMaxDynamicSharedMemorySize, 98688);
        smem_set = 1;
    }

    init_states<<<256, 256>>>(z, fhw, fhb, fcw, fcb, fiw, fib);
    init_gx0<<<256, 256>>>(Wih0, bih0, bhh0, bih1, bhh1);
    lstm_kernel<<<96, 128, 229376>>>(Whh0, Wih1, Whh1);
    proj_kernel<<<4096, 256, 98688>>>(Wout, bout, out);
}

// round 10
// speedup vs baseline: 2.0568x; 1.5411x over previous
#include <cuda_runtime.h>
#include <cuda_fp16.h>
#include <math.h>
#include <stdint.h>

typedef unsigned long long u64;
typedef unsigned int u32;

// ---------------------------------------------------------------------------
// Device-global scratch. Hidden rings split fp16 (hi+lo, exact to 2^-22),
// slot-major [slot][B][H]; slot 0 = initial state, slot s = output of step s-1.
// Slot-unique addresses -> no stale-L1 hazard across the software barrier.
// ---------------------------------------------------------------------------
#define RING_ELEMS (513 * 256 * 256)
__device__ __align__(256) __half g_h0hi[RING_ELEMS];
__device__ __align__(256) __half g_h0lo[RING_ELEMS];
__device__ __align__(256) __half g_h1hi[RING_ELEMS];
__device__ __align__(256) __half g_h1lo[RING_ELEMS];
__device__ __align__(256) float g_c0[256 * 256];
__device__ __align__(256) float g_c1[256 * 256];
__device__ __align__(256) float g_x0[256 * 256];
__device__ __align__(256) float g_gx0[256 * 1024];   // x-proj + b_ih0 + b_hh0
__device__ __align__(256) float g_b1sum[1024];       // b_ih1 + b_hh1
// layer1 input-GEMM partials, double buffered by round parity:
// [parity][cta 0..31][nt 0..7][tid 0..255][4]
__device__ __align__(256) float g_p1[2][32][8192];
__device__ unsigned g_bar_arrive;
__device__ volatile unsigned g_bar_release;

// ---------------------------------------------------------------------------
// PTX helpers (sm_80-level only: must compile for virtual arch compute_103)
// ---------------------------------------------------------------------------
#define CPA16(s, g)  asm volatile("cp.async.ca.shared.global [%0], [%1], 16;" :: "r"(s), "l"(g))
#define CPA16CG(s, g) asm volatile("cp.async.cg.shared.global [%0], [%1], 16;" :: "r"(s), "l"(g))
#define CPCOMMIT()  asm volatile("cp.async.commit_group;")
#define CPWAIT2()   asm volatile("cp.async.wait_group 2;")
#define CPWAIT1()   asm volatile("cp.async.wait_group 1;")
#define CPWAIT0()   asm volatile("cp.async.wait_group 0;")

#define LDSM4(r, addr) \
    asm volatile("ldmatrix.sync.aligned.m8n8.x4.shared.b16 {%0,%1,%2,%3}, [%4];" \
        : "=r"((r)[0]), "=r"((r)[1]), "=r"((r)[2]), "=r"((r)[3]) : "r"(addr))

#define LDS64(b, addr) \
    asm volatile("ld.shared.v2.u32 {%0,%1}, [%2];" \
        : "=r"((b)[0]), "=r"((b)[1]) : "r"(addr))

#define MMA(d, a, b) \
    asm volatile("mma.sync.aligned.m16n8k16.row.col.f32.f16.f16.f32 " \
        "{%0,%1,%2,%3}, {%4,%5,%6,%7}, {%8,%9}, {%0,%1,%2,%3};" \
        : "+f"((d)[0]), "+f"((d)[1]), "+f"((d)[2]), "+f"((d)[3]) \
        : "r"((a)[0]), "r"((a)[1]), "r"((a)[2]), "r"((a)[3]), "r"((b)[0]), "r"((b)[1]))

__device__ __forceinline__ float sigf(float x) {
    x = fminf(fmaxf(x, -30.f), 30.f);
    return 1.f / (1.f + __expf(-x));
}
__device__ __forceinline__ float tanhfast(float x) {
    x = fminf(fmaxf(x, -15.f), 15.f);
    float e = __expf(2.f * x);
    return (e - 1.f) / (e + 1.f);
}

__device__ __forceinline__ void grid_sync(unsigned round) {
    __syncthreads();
    if (threadIdx.x == 0) {
        __threadfence();
        unsigned old = atomicAdd(&g_bar_arrive, 1u);
        if (old + 1u == round * gridDim.x) {
            g_bar_release = round;
            __threadfence();
        } else {
            while (g_bar_release < round) __nanosleep(16);
            __threadfence();
        }
    }
    __syncthreads();
}

// Weight fragment byte offset: element (n, k) of a 64 x 256 fp16 slice,
// fragment layout for mma B: per (ntile, kstep) block of 256B, lane-major.
__device__ __forceinline__ int wfrag_off(int n, int k) {
    int nt = n >> 3, s = k >> 4, kl = k & 15;
    int lw = ((n & 7) << 2) | ((kl & 7) >> 1);
    return (((nt * 16 + s) * 32 + lw) << 3) + ((kl >> 3) << 2) + ((kl & 1) << 1);
}

// ---------------------------------------------------------------------------
// Init kernel 1: initial hidden/cell states (ring slot 0, split fp16) + x0
// ---------------------------------------------------------------------------
__global__ void __launch_bounds__(256) init_states(
    const float* __restrict__ z,
    const float* __restrict__ Wh, const float* __restrict__ bh,
    const float* __restrict__ Wc, const float* __restrict__ bc,
    const float* __restrict__ Wx, const float* __restrict__ bx)
{
    __shared__ float zs[128];
    const int b = blockIdx.x, tid = threadIdx.x;
    if (tid < 128) zs[tid] = z[b * 128 + tid];
    __syncthreads();
#pragma unroll
    for (int rep = 0; rep < 2; ++rep) {
        int c = tid + (rep << 8);
        float sh = bh[c], sc = bc[c];
        const float4* wh4 = (const float4*)(Wh + c * 128);
        const float4* wc4 = (const float4*)(Wc + c * 128);
#pragma unroll 8
        for (int k = 0; k < 32; ++k) {
            float4 a = wh4[k], d = wc4[k];
            float z0 = zs[4 * k], z1 = zs[4 * k + 1], z2 = zs[4 * k + 2], z3 = zs[4 * k + 3];
            sh += a.x * z0 + a.y * z1 + a.z * z2 + a.w * z3;
            sc += d.x * z0 + d.y * z1 + d.z * z2 + d.w * z3;
        }
        __half hi = __float2half(sh);
        __half lo = __float2half(sh - __half2float(hi));
        if (c < 256) {
            g_h0hi[b * 256 + c] = hi; g_h0lo[b * 256 + c] = lo;
            g_c0[b * 256 + c] = sc;
        } else {
            g_h1hi[b * 256 + c - 256] = hi; g_h1lo[b * 256 + c - 256] = lo;
            g_c1[b * 256 + c - 256] = sc;
        }
    }
    {
        int c = tid;
        float s = bx[c];
        const float4* w4 = (const float4*)(Wx + c * 128);
#pragma unroll 8
        for (int k = 0; k < 32; ++k) {
            float4 a = w4[k];
            s += a.x * zs[4 * k] + a.y * zs[4 * k + 1] + a.z * zs[4 * k + 2] + a.w * zs[4 * k + 3];
        }
        g_x0[b * 256 + c] = s;
    }
}

// ---------------------------------------------------------------------------
// Init kernel 2: gx0 = x0 @ W_ih0^T + b_ih0 + b_hh0 ; b1sum ; barrier reset
// ---------------------------------------------------------------------------
__global__ void __launch_bounds__(256) init_gx0(
    const float* __restrict__ Wih0, const float* __restrict__ bih0, const float* __restrict__ bhh0,
    const float* __restrict__ bih1, const float* __restrict__ bhh1)
{
    __shared__ float xs[256];
    const int b = blockIdx.x, tid = threadIdx.x;
    xs[tid] = g_x0[b * 256 + tid];
    __syncthreads();
#pragma unroll
    for (int q = 0; q < 4; ++q) {
        int c = (q << 8) + tid;
        float s = bih0[c] + bhh0[c];
        const float4* w4 = (const float4*)(Wih0 + c * 256);
#pragma unroll 8
        for (int k = 0; k < 64; ++k) {
            float4 a = w4[k];
            s += a.x * xs[4 * k] + a.y * xs[4 * k + 1] + a.z * xs[4 * k + 2] + a.w * xs[4 * k + 3];
        }
        g_gx0[b * 1024 + c] = s;
    }
    if (b == 0) {
#pragma unroll
        for (int q = 0; q < 4; ++q) { int c = (q << 8) + tid; g_b1sum[c] = bih1[c] + bhh1[c]; }
        if (tid == 0) { g_bar_arrive = 0; g_bar_release = 0; }
    }
}

// ---------------------------------------------------------------------------
// Stage A tile: 128 rows x 256 fp16 (hi+lo, 64KB each) -> smem, XOR-swizzled
// 16B chunks (c ^ (row & 7)). One k-half (128 k) per call: 16 CPA16/thread.
// ---------------------------------------------------------------------------
__device__ __forceinline__ void stage_half(
    u32 Ah_sa, u32 Al_sa, const char* sh, const char* sl, int tid, int half)
{
#pragma unroll
    for (int it = 0; it < 8; ++it) {
        int idq = tid + (it << 8);          // 0..2047
        int row = idq >> 4;
        int c = (idq & 15) + half * 16;     // 16B chunk within 512B row
        u32 d = (u32)row * 512u + (u32)((c ^ (row & 7)) << 4);
        u32 so = (u32)row * 512u + (u32)(c << 4);
        CPA16(Ah_sa + d, sh + so);
        CPA16(Al_sa + d, sl + so);
    }
    CPCOMMIT();
}

// 2-term fp16 GEMM over 8 k-steps: acc[nt] += Ahi*W + Alo*W
__device__ __forceinline__ void compute8(
    float (&acc)[8][4], int s0, u32 Ah_sa, u32 Al_sa, u32 Wf_sa,
    u32 rb, u32 chs, u32 rsw, u32 bl8)
{
#pragma unroll 1
    for (int ss = 0; ss < 8; ++ss) {
        int s = s0 + ss;
        u32 so = (u32)((((u32)(s << 1) + chs) ^ rsw) << 4);
        u32 ah[4], al[4];
        LDSM4(ah, Ah_sa + rb + so);
        LDSM4(al, Al_sa + rb + so);
#pragma unroll
        for (int nt = 0; nt < 8; ++nt) {
            u32 wv[2];
            LDS64(wv, Wf_sa + (u32)((nt * 16 + s) << 8) + bl8);
            MMA(acc[nt], ah, wv);
            MMA(acc[nt], al, wv);
        }
    }
}

// ---------------------------------------------------------------------------
// Persistent LSTM kernel: 96 CTAs x 256 threads (8 warps), 3 groups of 32.
//   G0 (bid 0..31) : gates0 = h0[r-1]*Whh0 (+gx0) -> pointwise -> h0[r]
//   G1 (bid 32..63): p1 = h0[r-1]*Wih1 -> global partial buf[r&1]
//   G2 (bid 64..95): p2 = h1[r-3]*Whh1 ; + p1(buf[(r-1)&1]) + b1 -> h1[r-2]
// Tile per CTA: M=128 (m = c&1 batch half) x N=64 (j0 = (c>>1)*16,
// col = gate*16 + jj). Warp w owns rows w*16..w*16+15. 514 rounds.
// ---------------------------------------------------------------------------
__global__ void __launch_bounds__(256, 1) lstm_kernel(
    const float* __restrict__ Whh0f,
    const float* __restrict__ Wih1f,
    const float* __restrict__ Whh1f)
{
    extern __shared__ char smA[];
    const u32 smb = (u32)__cvta_generic_to_shared(smA);
    const u32 Ah_sa = smb;                 // 64 KB
    const u32 Al_sa = smb + 65536u;        // 64 KB
    const u32 Wf_sa = smb + 131072u;       // 32 KB (fp16 weight fragments)
    const u32 aux_sa = smb + 163840u;      // 32 KB (G0: gxs / G2: p1 tile)
    char* Wf = smA + 131072;
    float* gxs = (float*)(smA + 163840);

    const int tid = threadIdx.x;
    const int lane = tid & 31, w = tid >> 5;
    const int group = blockIdx.x >> 5;     // 0,1,2
    const int c = blockIdx.x & 31;
    const int m = c & 1;
    const int j0 = (c >> 1) << 4;
    const int q = lane >> 2;
    const int c2 = (lane & 3) << 1;

    // ldmatrix / fragment addressing
    const int rA = (lane & 7) + (((lane >> 3) & 1) << 3);
    const u32 chs = (u32)(lane >> 4);
    const u32 rsw = (u32)(lane & 7);
    const u32 rb = (u32)(w * 16 + rA) * 512u;
    const u32 bl8 = (u32)lane * 8u;

    // ---- one-time weight fragment staging (fp32 -> single fp16) ----
    {
        const float* Wsrc = (group == 0) ? Whh0f : (group == 1) ? Wih1f : Whh1f;
        for (int e = tid; e < 16384; e += 256) {
            int n = e >> 8, k = e & 255;
            int wr = (n >> 4) * 256 + j0 + (n & 15);   // n = gate*16 + jj
            *(__half*)(Wf + wfrag_off(n, k)) = __float2half(Wsrc[wr * 256 + k]);
        }
    }

    // ---- sequence-invariant per-thread state ----
    float cval[8];
    float b1v[16];
    if (group == 0) {
        for (int e = tid; e < 8192; e += 256) {
            int i = e >> 8, t = e & 255;
            int nt = i >> 2, ib = i & 3, rh = ib >> 1, ee = ib & 1;
            int lt = t & 31, wt = t >> 5;
            int row = m * 128 + wt * 16 + rh * 8 + (lt >> 2);
            int col = j0 + (nt & 1) * 8 + ((lt & 3) << 1) + ee;
            gxs[i * 256 + t] = g_gx0[row * 1024 + (nt >> 1) * 256 + col];
        }
#pragma unroll
        for (int rh = 0; rh < 2; ++rh) {
            int row = m * 128 + w * 16 + rh * 8 + q;
#pragma unroll
            for (int nth = 0; nth < 2; ++nth)
#pragma unroll
                for (int e = 0; e < 2; ++e)
                    cval[rh * 4 + nth * 2 + e] = g_c0[row * 256 + j0 + nth * 8 + c2 + e];
        }
    } else if (group == 2) {
#pragma unroll
        for (int rh = 0; rh < 2; ++rh) {
            int row = m * 128 + w * 16 + rh * 8 + q;
#pragma unroll
            for (int nth = 0; nth < 2; ++nth)
#pragma unroll
                for (int e = 0; e < 2; ++e)
                    cval[rh * 4 + nth * 2 + e] = g_c1[row * 256 + j0 + nth * 8 + c2 + e];
        }
#pragma unroll
        for (int nt = 0; nt < 8; ++nt)
#pragma unroll
            for (int e = 0; e < 2; ++e)
                b1v[nt * 2 + e] = g_b1sum[(nt >> 1) * 256 + j0 + (nt & 1) * 8 + c2 + e];
    }
    __syncthreads();

#pragma unroll 1
    for (int r = 1; r <= 514; ++r) {
        if (group == 0) {
            // ============ LAYER 0 recurrent + pointwise ============
            if (r <= 512) {
                float acc[8][4];
#pragma unroll
                for (int nt = 0; nt < 8; ++nt)
#pragma unroll
                    for (int i = 0; i < 4; ++i) acc[nt][i] = 0.f;

                size_t rbase = (size_t)(r - 1) * 65536u + (size_t)m * 32768u;
                stage_half(Ah_sa, Al_sa, (const char*)(g_h0hi + rbase), (const char*)(g_h0lo + rbase), tid, 0);
                stage_half(Ah_sa, Al_sa, (const char*)(g_h0hi + rbase), (const char*)(g_h0lo + rbase), tid, 1);
                CPWAIT1(); __syncthreads();
                compute8(acc, 0, Ah_sa, Al_sa, Wf_sa, rb, chs, rsw, bl8);
                CPWAIT0(); __syncthreads();
                compute8(acc, 8, Ah_sa, Al_sa, Wf_sa, rb, chs, rsw, bl8);

                size_t os = (size_t)r * 65536u;
#pragma unroll
                for (int rh = 0; rh < 2; ++rh) {
                    int row = m * 128 + w * 16 + rh * 8 + q;
#pragma unroll
                    for (int nth = 0; nth < 2; ++nth) {
                        float hvv[2];
#pragma unroll
                        for (int e = 0; e < 2; ++e) {
                            int ci = rh * 4 + nth * 2 + e;
                            int ib = rh * 2 + e;
                            float pi = acc[0 + nth][ib] + gxs[((0 + nth) * 4 + ib) * 256 + tid];
                            float pf = acc[2 + nth][ib] + gxs[((2 + nth) * 4 + ib) * 256 + tid];
                            float pg = acc[4 + nth][ib] + gxs[((4 + nth) * 4 + ib) * 256 + tid];
                            float po = acc[6 + nth][ib] + gxs[((6 + nth) * 4 + ib) * 256 + tid];
                            float ig = sigf(pi), fg = sigf(pf), gg = tanhfast(pg), og = sigf(po);
                            cval[ci] = fg * cval[ci] + ig * gg;
                            hvv[e] = og * tanhfast(cval[ci]);
                        }
                        int col = j0 + nth * 8 + c2;
                        __half h0b = __float2half(hvv[0]);
                        __half h1b = __float2half(hvv[1]);
                        __half l0b = __float2half(hvv[0] - __half2float(h0b));
                        __half l1b = __float2half(hvv[1] - __half2float(h1b));
                        u32 ph = ((u32)__half_as_ushort(h1b) << 16) | (u32)__half_as_ushort(h0b);
                        u32 pl = ((u32)__half_as_ushort(l1b) << 16) | (u32)__half_as_ushort(l0b);
                        *(u32*)(g_h0hi + os + (size_t)row * 256 + col) = ph;
                        *(u32*)(g_h0lo + os + (size_t)row * 256 + col) = pl;
                    }
                }
            }
        } else if (group == 1) {
            // ============ LAYER 1 input GEMM -> partial ============
            if (r >= 2 && r <= 513) {
                float acc[8][4];
#pragma unroll
                for (int nt = 0; nt < 8; ++nt)
#pragma unroll
                    for (int i = 0; i < 4; ++i) acc[nt][i] = 0.f;

                size_t rbase = (size_t)(r - 1) * 65536u + (size_t)m * 32768u;
                stage_half(Ah_sa, Al_sa, (const char*)(g_h0hi + rbase), (const char*)(g_h0lo + rbase), tid, 0);
                stage_half(Ah_sa, Al_sa, (const char*)(g_h0hi + rbase), (const char*)(g_h0lo + rbase), tid, 1);
                CPWAIT1(); __syncthreads();
                compute8(acc, 0, Ah_sa, Al_sa, Wf_sa, rb, chs, rsw, bl8);
                CPWAIT0(); __syncthreads();
                compute8(acc, 8, Ah_sa, Al_sa, Wf_sa, rb, chs, rsw, bl8);

                float* dst = &g_p1[r & 1][c][0];
#pragma unroll
                for (int nt = 0; nt < 8; ++nt)
                    *(float4*)(dst + (((u32)nt << 8) + (u32)tid) * 4u) =
                        make_float4(acc[nt][0], acc[nt][1], acc[nt][2], acc[nt][3]);
            }
        } else {
            // ============ LAYER 1 recurrent + combine + pointwise ============
            if (r >= 3) {
                float acc[8][4];
#pragma unroll
                for (int nt = 0; nt < 8; ++nt)
#pragma unroll
                    for (int i = 0; i < 4; ++i) acc[nt][i] = 0.f;

                size_t rbase = (size_t)(r - 3) * 65536u + (size_t)m * 32768u;
                stage_half(Ah_sa, Al_sa, (const char*)(g_h1hi + rbase), (const char*)(g_h1lo + rbase), tid, 0);
                stage_half(Ah_sa, Al_sa, (const char*)(g_h1hi + rbase), (const char*)(g_h1lo + rbase), tid, 1);
                // p1 partial tile -> smem (L2-only: buffer addresses recycle)
                {
                    const char* src = (const char*)&g_p1[(r - 1) & 1][c][0];
#pragma unroll
                    for (int it = 0; it < 8; ++it) {
                        u32 off = (u32)(tid + (it << 8)) * 16u;
                        CPA16CG(aux_sa + off, src + off);
                    }
                    CPCOMMIT();
                }
                CPWAIT2(); __syncthreads();
                compute8(acc, 0, Ah_sa, Al_sa, Wf_sa, rb, chs, rsw, bl8);
                CPWAIT1(); __syncthreads();
                compute8(acc, 8, Ah_sa, Al_sa, Wf_sa, rb, chs, rsw, bl8);
                CPWAIT0();   // p1 landed (each thread reads only its own chunks)

                const float* p1s = (const float*)(smA + 163840);
                size_t os = (size_t)(r - 2) * 65536u;
#pragma unroll
                for (int rh = 0; rh < 2; ++rh) {
                    int row = m * 128 + w * 16 + rh * 8 + q;
#pragma unroll
                    for (int nth = 0; nth < 2; ++nth) {
                        float hvv[2];
#pragma unroll
                        for (int e = 0; e < 2; ++e) {
                            int ci = rh * 4 + nth * 2 + e;
                            int ib = rh * 2 + e;
                            float pi = acc[0 + nth][ib] + p1s[(((0 + nth) << 8) + tid) * 4 + ib] + b1v[(0 + nth) * 2 + e];
                            float pf = acc[2 + nth][ib] + p1s[(((2 + nth) << 8) + tid) * 4 + ib] + b1v[(2 + nth) * 2 + e];
                            float pg = acc[4 + nth][ib] + p1s[(((4 + nth) << 8) + tid) * 4 + ib] + b1v[(4 + nth) * 2 + e];
                            float po = acc[6 + nth][ib] + p1s[(((6 + nth) << 8) + tid) * 4 + ib] + b1v[(6 + nth) * 2 + e];
                            float ig = sigf(pi), fg = sigf(pf), gg = tanhfast(pg), og = sigf(po);
                            cval[ci] = fg * cval[ci] + ig * gg;
                            hvv[e] = og * tanhfast(cval[ci]);
                        }
                        int col = j0 + nth * 8 + c2;
                        __half h0b = __float2half(hvv[0]);
                        __half h1b = __float2half(hvv[1]);
                        __half l0b = __float2half(hvv[0] - __half2float(h0b));
                        __half l1b = __float2half(hvv[1] - __half2float(h1b));
                        u32 ph = ((u32)__half_as_ushort(h1b) << 16) | (u32)__half_as_ushort(h0b);
                        u32 pl = ((u32)__half_as_ushort(l1b) << 16) | (u32)__half_as_ushort(l0b);
                        *(u32*)(g_h1hi + os + (size_t)row * 256 + col) = ph;
                        *(u32*)(g_h1lo + os + (size_t)row * 256 + col) = pl;
                    }
                }
            }
        }
        grid_sync((unsigned)r);
    }
}

// ---------------------------------------------------------------------------
// Output projection: out[b,s,:64] = (h1hi+h1lo)[b,s,:] @ Wout^T + bout
// ---------------------------------------------------------------------------
__global__ void __launch_bounds__(256) proj_kernel(
    const float* __restrict__ Wout, const float* __restrict__ bout,
    float* __restrict__ out)
{
    extern __shared__ float smP[];
    float* ws = smP;              // [64][257]
    float* hsr = smP + 64 * 257;  // [32][257]
    const int tid = threadIdx.x;
    const int lin0 = blockIdx.x * 32;

    for (int i = tid; i < 64 * 64; i += 256) {
        int row = i >> 6, k4 = i & 63;
        float4 v = ((const float4*)(Wout + row * 256))[k4];
        float* d = ws + row * 257 + k4 * 4;
        d[0] = v.x; d[1] = v.y; d[2] = v.z; d[3] = v.w;
    }
    for (int i = tid; i < 32 * 32; i += 256) {
        int rr = i >> 5, ch = i & 31;
        int lin = lin0 + rr, b = lin >> 9, s = lin & 511;
        size_t off = (size_t)(s + 1) * 65536u + (size_t)b * 256u + (size_t)ch * 8u;
        uint4 vh = *(const uint4*)(g_h1hi + off);
        uint4 vl = *(const uint4*)(g_h1lo + off);
        const __half* ph = (const __half*)&vh;
        const __half* pl = (const __half*)&vl;
        float* d = hsr + rr * 257 + ch * 8;
#pragma unroll
        for (int k = 0; k < 8; ++k)
            d[k] = __half2float(ph[k]) + __half2float(pl[k]);
    }
    __syncthreads();

    const int o = tid & 63, rg = tid >> 6;
    float acc[8];
    float bb = bout[o];
#pragma unroll
    for (int ri = 0; ri < 8; ++ri) acc[ri] = bb;
    const float* wrow = ws + o * 257;
    const float* hbase = hsr + (rg * 8) * 257;
#pragma unroll 4
    for (int k = 0; k < 256; ++k) {
        float wv = wrow[k];
#pragma unroll
        for (int ri = 0; ri < 8; ++ri) acc[ri] += hbase[ri * 257 + k] * wv;
    }
#pragma unroll
    for (int ri = 0; ri < 8; ++ri) {
        int lin = lin0 + rg * 8 + ri;
        out[(unsigned)lin * 64u + o] = acc[ri];
    }
}

// ---------------------------------------------------------------------------
// kernel_launch
// ---------------------------------------------------------------------------
extern "C" void kernel_launch(void* const* d_in, const int* in_sizes, int n_in,
                              void* d_out, int out_size)
{
    const float* z    = (const float*)d_in[0];
    const float* fhw  = (const float*)d_in[1];
    const float* fhb  = (const float*)d_in[2];
    const float* fcw  = (const float*)d_in[3];
    const float* fcb  = (const float*)d_in[4];
    const float* fiw  = (const float*)d_in[5];
    const float* fib  = (const float*)d_in[6];
    const float* Wih0 = (const float*)d_in[7];
    const float* Whh0 = (const float*)d_in[8];
    const float* bih0 = (const float*)d_in[9];
    const float* bhh0 = (const float*)d_in[10];
    const float* Wih1 = (const float*)d_in[11];
    const float* Whh1 = (const float*)d_in[12];
    const float* bih1 = (const float*)d_in[13];
    const float* bhh1 = (const float*)d_in[14];
    const float* Wout = (const float*)d_in[15];
    const float* bout = (const float*)d_in[16];
    float* out = (float*)d_out;

    static int smem_set = 0;
    if (!smem_set) {
        cudaFuncSetAttribute(lstm_kernel, cudaFuncAttributeMaxDynamicSharedMemorySize, 196608);
        cudaFuncSetAttribute(proj_kernel, cudaFuncAttributeMaxDynamicSharedMemorySize, 98688);
        smem_set = 1;
    }

    init_states<<<256, 256>>>(z, fhw, fhb, fcw, fcb, fiw, fib);
    init_gx0<<<256, 256>>>(Wih0, bih0, bhh0, bih1, bhh1);
    lstm_kernel<<<96, 256, 196608>>>(Whh0, Wih1, Whh1);
    proj_kernel<<<4096, 256, 98688>>>(Wout, bout, out);
}

// round 11
// speedup vs baseline: 2.4013x; 1.1675x over previous
#include <cuda_runtime.h>
#include <cuda_fp16.h>
#include <math.h>
#include <stdint.h>

typedef unsigned long long u64;
typedef unsigned int u32;

// ---------------------------------------------------------------------------
// Device-global scratch. Hidden rings single fp16, slot-major [slot][B][H];
// slot 0 = initial state, slot s = output of step s-1. Slot-unique addresses
// -> no stale-L1 hazard across the software barrier.
// ---------------------------------------------------------------------------
#define RING_ELEMS (513 * 256 * 256)
__device__ __align__(256) __half g_h0hi[RING_ELEMS];
__device__ __align__(256) __half g_h1hi[RING_ELEMS];
__device__ __align__(256) float g_c0[256 * 256];
__device__ __align__(256) float g_c1[256 * 256];
__device__ __align__(256) float g_x0[256 * 256];
__device__ __align__(256) float g_gx0[256 * 1024];   // x-proj + b_ih0 + b_hh0
__device__ __align__(256) float g_b1sum[1024];       // b_ih1 + b_hh1
// layer1 input-GEMM partials, double buffered by round parity:
// [parity][cta 0..31][nt 0..7][tid 0..255][4]
__device__ __align__(256) float g_p1[2][32][8192];
__device__ unsigned g_bar_arrive;
__device__ volatile unsigned g_bar_release;

// ---------------------------------------------------------------------------
// PTX helpers (sm_80-level only: must compile for virtual arch compute_103)
// ---------------------------------------------------------------------------
#define CPA16(s, g)  asm volatile("cp.async.ca.shared.global [%0], [%1], 16;" :: "r"(s), "l"(g))
#define CPA16CG(s, g) asm volatile("cp.async.cg.shared.global [%0], [%1], 16;" :: "r"(s), "l"(g))
#define CPCOMMIT()  asm volatile("cp.async.commit_group;")
#define CPWAIT2()   asm volatile("cp.async.wait_group 2;")
#define CPWAIT1()   asm volatile("cp.async.wait_group 1;")
#define CPWAIT0()   asm volatile("cp.async.wait_group 0;")

#define LDSM4(r, addr) \
    asm volatile("ldmatrix.sync.aligned.m8n8.x4.shared.b16 {%0,%1,%2,%3}, [%4];" \
        : "=r"((r)[0]), "=r"((r)[1]), "=r"((r)[2]), "=r"((r)[3]) : "r"(addr))

#define LDS64(b, addr) \
    asm volatile("ld.shared.v2.u32 {%0,%1}, [%2];" \
        : "=r"((b)[0]), "=r"((b)[1]) : "r"(addr))

#define MMA(d, a, b) \
    asm volatile("mma.sync.aligned.m16n8k16.row.col.f32.f16.f16.f32 " \
        "{%0,%1,%2,%3}, {%4,%5,%6,%7}, {%8,%9}, {%0,%1,%2,%3};" \
        : "+f"((d)[0]), "+f"((d)[1]), "+f"((d)[2]), "+f"((d)[3]) \
        : "r"((a)[0]), "r"((a)[1]), "r"((a)[2]), "r"((a)[3]), "r"((b)[0]), "r"((b)[1]))

__device__ __forceinline__ float sigf(float x) {
    x = fminf(fmaxf(x, -30.f), 30.f);
    return 1.f / (1.f + __expf(-x));
}
__device__ __forceinline__ float tanhfast(float x) {
    x = fminf(fmaxf(x, -15.f), 15.f);
    float e = __expf(2.f * x);
    return (e - 1.f) / (e + 1.f);
}

__device__ __forceinline__ void grid_sync(unsigned round) {
    __syncthreads();
    if (threadIdx.x == 0) {
        __threadfence();
        unsigned old = atomicAdd(&g_bar_arrive, 1u);
        if (old + 1u == round * gridDim.x) {
            g_bar_release = round;
            __threadfence();
        } else {
            while (g_bar_release < round) __nanosleep(16);
            __threadfence();
        }
    }
    __syncthreads();
}

// Weight fragment byte offset: element (n, k) of a 64 x 256 fp16 slice,
// fragment layout for mma B: per (ntile, kstep) block of 256B, lane-major.
__device__ __forceinline__ int wfrag_off(int n, int k) {
    int nt = n >> 3, s = k >> 4, kl = k & 15;
    int lw = ((n & 7) << 2) | ((kl & 7) >> 1);
    return (((nt * 16 + s) * 32 + lw) << 3) + ((kl >> 3) << 2) + ((kl & 1) << 1);
}

// ---------------------------------------------------------------------------
// Init kernel 1: initial hidden/cell states (ring slot 0, fp16) + x0
// ---------------------------------------------------------------------------
__global__ void __launch_bounds__(256) init_states(
    const float* __restrict__ z,
    const float* __restrict__ Wh, const float* __restrict__ bh,
    const float* __restrict__ Wc, const float* __restrict__ bc,
    const float* __restrict__ Wx, const float* __restrict__ bx)
{
    __shared__ float zs[128];
    const int b = blockIdx.x, tid = threadIdx.x;
    if (tid < 128) zs[tid] = z[b * 128 + tid];
    __syncthreads();
#pragma unroll
    for (int rep = 0; rep < 2; ++rep) {
        int c = tid + (rep << 8);
        float sh = bh[c], sc = bc[c];
        const float4* wh4 = (const float4*)(Wh + c * 128);
        const float4* wc4 = (const float4*)(Wc + c * 128);
#pragma unroll 8
        for (int k = 0; k < 32; ++k) {
            float4 a = wh4[k], d = wc4[k];
            float z0 = zs[4 * k], z1 = zs[4 * k + 1], z2 = zs[4 * k + 2], z3 = zs[4 * k + 3];
            sh += a.x * z0 + a.y * z1 + a.z * z2 + a.w * z3;
            sc += d.x * z0 + d.y * z1 + d.z * z2 + d.w * z3;
        }
        if (c < 256) {
            g_h0hi[b * 256 + c] = __float2half(sh);
            g_c0[b * 256 + c] = sc;
        } else {
            g_h1hi[b * 256 + c - 256] = __float2half(sh);
            g_c1[b * 256 + c - 256] = sc;
        }
    }
    {
        int c = tid;
        float s = bx[c];
        const float4* w4 = (const float4*)(Wx + c * 128);
#pragma unroll 8
        for (int k = 0; k < 32; ++k) {
            float4 a = w4[k];
            s += a.x * zs[4 * k] + a.y * zs[4 * k + 1] + a.z * zs[4 * k + 2] + a.w * zs[4 * k + 3];
        }
        g_x0[b * 256 + c] = s;
    }
}

// ---------------------------------------------------------------------------
// Init kernel 2: gx0 = x0 @ W_ih0^T + b_ih0 + b_hh0 ; b1sum ; barrier reset
// ---------------------------------------------------------------------------
__global__ void __launch_bounds__(256) init_gx0(
    const float* __restrict__ Wih0, const float* __restrict__ bih0, const float* __restrict__ bhh0,
    const float* __restrict__ bih1, const float* __restrict__ bhh1)
{
    __shared__ float xs[256];
    const int b = blockIdx.x, tid = threadIdx.x;
    xs[tid] = g_x0[b * 256 + tid];
    __syncthreads();
#pragma unroll
    for (int q = 0; q < 4; ++q) {
        int c = (q << 8) + tid;
        float s = bih0[c] + bhh0[c];
        const float4* w4 = (const float4*)(Wih0 + c * 256);
#pragma unroll 8
        for (int k = 0; k < 64; ++k) {
            float4 a = w4[k];
            s += a.x * xs[4 * k] + a.y * xs[4 * k + 1] + a.z * xs[4 * k + 2] + a.w * xs[4 * k + 3];
        }
        g_gx0[b * 1024 + c] = s;
    }
    if (b == 0) {
#pragma unroll
        for (int q = 0; q < 4; ++q) { int c = (q << 8) + tid; g_b1sum[c] = bih1[c] + bhh1[c]; }
        if (tid == 0) { g_bar_arrive = 0; g_bar_release = 0; }
    }
}

// ---------------------------------------------------------------------------
// Stage A k-half: 128 rows x 128 fp16 -> smem, XOR-swizzled 16B chunks.
// 8 CPA16 per thread per call.
// ---------------------------------------------------------------------------
__device__ __forceinline__ void stage_half(
    u32 Ah_sa, const char* sh, int tid, int half)
{
#pragma unroll
    for (int it = 0; it < 8; ++it) {
        int idq = tid + (it << 8);          // 0..2047
        int row = idq >> 4;
        int c = (idq & 15) + half * 16;     // 16B chunk within 512B row
        u32 d = (u32)row * 512u + (u32)((c ^ (row & 7)) << 4);
        u32 so = (u32)row * 512u + (u32)(c << 4);
        CPA16(Ah_sa + d, sh + so);
    }
    CPCOMMIT();
}

// 1-term fp16 GEMM over 8 k-steps: acc[nt] += A*W
__device__ __forceinline__ void compute8(
    float (&acc)[8][4], int s0, u32 Ah_sa, u32 Wf_sa,
    u32 rb, u32 chs, u32 rsw, u32 bl8)
{
#pragma unroll 1
    for (int ss = 0; ss < 8; ++ss) {
        int s = s0 + ss;
        u32 so = (u32)((((u32)(s << 1) + chs) ^ rsw) << 4);
        u32 ah[4];
        LDSM4(ah, Ah_sa + rb + so);
#pragma unroll
        for (int nt = 0; nt < 8; ++nt) {
            u32 wv[2];
            LDS64(wv, Wf_sa + (u32)((nt * 16 + s) << 8) + bl8);
            MMA(acc[nt], ah, wv);
        }
    }
}

// ---------------------------------------------------------------------------
// Persistent LSTM kernel: 96 CTAs x 256 threads (8 warps), 3 groups of 32.
//   G0 (bid 0..31) : gates0 = h0[r-1]*Whh0 (+gx0) -> pointwise -> h0[r]
//   G1 (bid 32..63): p1 = h0[r-1]*Wih1 -> global partial buf[r&1]
//   G2 (bid 64..95): p2 = h1[r-3]*Whh1 ; + p1(buf[(r-1)&1]) + b1 -> h1[r-2]
// Tile per CTA: M=128 (m = c&1 batch half) x N=64 (j0 = (c>>1)*16,
// col = gate*16 + jj). Warp w owns rows w*16..w*16+15. 514 rounds.
// ---------------------------------------------------------------------------
__global__ void __launch_bounds__(256, 1) lstm_kernel(
    const float* __restrict__ Whh0f,
    const float* __restrict__ Wih1f,
    const float* __restrict__ Whh1f)
{
    extern __shared__ char smA[];
    const u32 smb = (u32)__cvta_generic_to_shared(smA);
    const u32 Ah_sa = smb;                 // 64 KB (fp16 A tile)
    const u32 Wf_sa = smb + 65536u;        // 32 KB (fp16 weight fragments)
    const u32 aux_sa = smb + 98304u;       // 32 KB (G0: gxs / G2: p1 tile)
    char* Wf = smA + 65536;
    float* gxs = (float*)(smA + 98304);

    const int tid = threadIdx.x;
    const int lane = tid & 31, w = tid >> 5;
    const int group = blockIdx.x >> 5;     // 0,1,2
    const int c = blockIdx.x & 31;
    const int m = c & 1;
    const int j0 = (c >> 1) << 4;
    const int q = lane >> 2;
    const int c2 = (lane & 3) << 1;

    // ldmatrix / fragment addressing
    const int rA = (lane & 7) + (((lane >> 3) & 1) << 3);
    const u32 chs = (u32)(lane >> 4);
    const u32 rsw = (u32)(lane & 7);
    const u32 rb = (u32)(w * 16 + rA) * 512u;
    const u32 bl8 = (u32)lane * 8u;

    // ---- one-time weight fragment staging (fp32 -> single fp16) ----
    {
        const float* Wsrc = (group == 0) ? Whh0f : (group == 1) ? Wih1f : Whh1f;
        for (int e = tid; e < 16384; e += 256) {
            int n = e >> 8, k = e & 255;
            int wr = (n >> 4) * 256 + j0 + (n & 15);   // n = gate*16 + jj
            *(__half*)(Wf + wfrag_off(n, k)) = __float2half(Wsrc[wr * 256 + k]);
        }
    }

    // ---- sequence-invariant per-thread state ----
    float cval[8];
    float b1v[16];
    if (group == 0) {
        for (int e = tid; e < 8192; e += 256) {
            int i = e >> 8, t = e & 255;
            int nt = i >> 2, ib = i & 3, rh = ib >> 1, ee = ib & 1;
            int lt = t & 31, wt = t >> 5;
            int row = m * 128 + wt * 16 + rh * 8 + (lt >> 2);
            int col = j0 + (nt & 1) * 8 + ((lt & 3) << 1) + ee;
            gxs[i * 256 + t] = g_gx0[row * 1024 + (nt >> 1) * 256 + col];
        }
#pragma unroll
        for (int rh = 0; rh < 2; ++rh) {
            int row = m * 128 + w * 16 + rh * 8 + q;
#pragma unroll
            for (int nth = 0; nth < 2; ++nth)
#pragma unroll
                for (int e = 0; e < 2; ++e)
                    cval[rh * 4 + nth * 2 + e] = g_c0[row * 256 + j0 + nth * 8 + c2 + e];
        }
    } else if (group == 2) {
#pragma unroll
        for (int rh = 0; rh < 2; ++rh) {
            int row = m * 128 + w * 16 + rh * 8 + q;
#pragma unroll
            for (int nth = 0; nth < 2; ++nth)
#pragma unroll
                for (int e = 0; e < 2; ++e)
                    cval[rh * 4 + nth * 2 + e] = g_c1[row * 256 + j0 + nth * 8 + c2 + e];
        }
#pragma unroll
        for (int nt = 0; nt < 8; ++nt)
#pragma unroll
            for (int e = 0; e < 2; ++e)
                b1v[nt * 2 + e] = g_b1sum[(nt >> 1) * 256 + j0 + (nt & 1) * 8 + c2 + e];
    }
    __syncthreads();

#pragma unroll 1
    for (int r = 1; r <= 514; ++r) {
        if (group == 0) {
            // ============ LAYER 0 recurrent + pointwise ============
            if (r <= 512) {
                float acc[8][4];
#pragma unroll
                for (int nt = 0; nt < 8; ++nt)
#pragma unroll
                    for (int i = 0; i < 4; ++i) acc[nt][i] = 0.f;

                size_t rbase = (size_t)(r - 1) * 65536u + (size_t)m * 32768u;
                stage_half(Ah_sa, (const char*)(g_h0hi + rbase), tid, 0);
                stage_half(Ah_sa, (const char*)(g_h0hi + rbase), tid, 1);
                CPWAIT1(); __syncthreads();
                compute8(acc, 0, Ah_sa, Wf_sa, rb, chs, rsw, bl8);
                CPWAIT0(); __syncthreads();
                compute8(acc, 8, Ah_sa, Wf_sa, rb, chs, rsw, bl8);

                size_t os = (size_t)r * 65536u;
#pragma unroll
                for (int rh = 0; rh < 2; ++rh) {
                    int row = m * 128 + w * 16 + rh * 8 + q;
#pragma unroll
                    for (int nth = 0; nth < 2; ++nth) {
                        float hvv[2];
#pragma unroll
                        for (int e = 0; e < 2; ++e) {
                            int ci = rh * 4 + nth * 2 + e;
                            int ib = rh * 2 + e;
                            float pi = acc[0 + nth][ib] + gxs[((0 + nth) * 4 + ib) * 256 + tid];
                            float pf = acc[2 + nth][ib] + gxs[((2 + nth) * 4 + ib) * 256 + tid];
                            float pg = acc[4 + nth][ib] + gxs[((4 + nth) * 4 + ib) * 256 + tid];
                            float po = acc[6 + nth][ib] + gxs[((6 + nth) * 4 + ib) * 256 + tid];
                            float ig = sigf(pi), fg = sigf(pf), gg = tanhfast(pg), og = sigf(po);
                            cval[ci] = fg * cval[ci] + ig * gg;
                            hvv[e] = og * tanhfast(cval[ci]);
                        }
                        int col = j0 + nth * 8 + c2;
                        __half h0b = __float2half(hvv[0]);
                        __half h1b = __float2half(hvv[1]);
                        u32 ph = ((u32)__half_as_ushort(h1b) << 16) | (u32)__half_as_ushort(h0b);
                        *(u32*)(g_h0hi + os + (size_t)row * 256 + col) = ph;
                    }
                }
            }
        } else if (group == 1) {
            // ============ LAYER 1 input GEMM -> partial ============
            if (r >= 2 && r <= 513) {
                float acc[8][4];
#pragma unroll
                for (int nt = 0; nt < 8; ++nt)
#pragma unroll
                    for (int i = 0; i < 4; ++i) acc[nt][i] = 0.f;

                size_t rbase = (size_t)(r - 1) * 65536u + (size_t)m * 32768u;
                stage_half(Ah_sa, (const char*)(g_h0hi + rbase), tid, 0);
                stage_half(Ah_sa, (const char*)(g_h0hi + rbase), tid, 1);
                CPWAIT1(); __syncthreads();
                compute8(acc, 0, Ah_sa, Wf_sa, rb, chs, rsw, bl8);
                CPWAIT0(); __syncthreads();
                compute8(acc, 8, Ah_sa, Wf_sa, rb, chs, rsw, bl8);

                float* dst = &g_p1[r & 1][c][0];
#pragma unroll
                for (int nt = 0; nt < 8; ++nt)
                    *(float4*)(dst + (((u32)nt << 8) + (u32)tid) * 4u) =
                        make_float4(acc[nt][0], acc[nt][1], acc[nt][2], acc[nt][3]);
            }
        } else {
            // ============ LAYER 1 recurrent + combine + pointwise ============
            if (r >= 3) {
                float acc[8][4];
#pragma unroll
                for (int nt = 0; nt < 8; ++nt)
#pragma unroll
                    for (int i = 0; i < 4; ++i) acc[nt][i] = 0.f;

                size_t rbase = (size_t)(r - 3) * 65536u + (size_t)m * 32768u;
                stage_half(Ah_sa, (const char*)(g_h1hi + rbase), tid, 0);
                stage_half(Ah_sa, (const char*)(g_h1hi + rbase), tid, 1);
                // p1 partial tile -> smem (L2-only: buffer addresses recycle)
                {
                    const char* src = (const char*)&g_p1[(r - 1) & 1][c][0];
#pragma unroll
                    for (int it = 0; it < 8; ++it) {
                        u32 off = (u32)(tid + (it << 8)) * 16u;
                        CPA16CG(aux_sa + off, src + off);
                    }
                    CPCOMMIT();
                }
                CPWAIT2(); __syncthreads();
                compute8(acc, 0, Ah_sa, Wf_sa, rb, chs, rsw, bl8);
                CPWAIT1(); __syncthreads();
                compute8(acc, 8, Ah_sa, Wf_sa, rb, chs, rsw, bl8);
                CPWAIT0();   // p1 landed (each thread reads only its own chunks)

                const float* p1s = (const float*)(smA + 98304);
                size_t os = (size_t)(r - 2) * 65536u;
#pragma unroll
                for (int rh = 0; rh < 2; ++rh) {
                    int row = m * 128 + w * 16 + rh * 8 + q;
#pragma unroll
                    for (int nth = 0; nth < 2; ++nth) {
                        float hvv[2];
#pragma unroll
                        for (int e = 0; e < 2; ++e) {
                            int ci = rh * 4 + nth * 2 + e;
                            int ib = rh * 2 + e;
                            float pi = acc[0 + nth][ib] + p1s[(((0 + nth) << 8) + tid) * 4 + ib] + b1v[(0 + nth) * 2 + e];
                            float pf = acc[2 + nth][ib] + p1s[(((2 + nth) << 8) + tid) * 4 + ib] + b1v[(2 + nth) * 2 + e];
                            float pg = acc[4 + nth][ib] + p1s[(((4 + nth) << 8) + tid) * 4 + ib] + b1v[(4 + nth) * 2 + e];
                            float po = acc[6 + nth][ib] + p1s[(((6 + nth) << 8) + tid) * 4 + ib] + b1v[(6 + nth) * 2 + e];
                            float ig = sigf(pi), fg = sigf(pf), gg = tanhfast(pg), og = sigf(po);
                            cval[ci] = fg * cval[ci] + ig * gg;
                            hvv[e] = og * tanhfast(cval[ci]);
                        }
                        int col = j0 + nth * 8 + c2;
                        __half h0b = __float2half(hvv[0]);
                        __half h1b = __float2half(hvv[1]);
                        u32 ph = ((u32)__half_as_ushort(h1b) << 16) | (u32)__half_as_ushort(h0b);
                        *(u32*)(g_h1hi + os + (size_t)row * 256 + col) = ph;
                    }
                }
            }
        }
        grid_sync((unsigned)r);
    }
}

// ---------------------------------------------------------------------------
// Output projection: out[b,s,:64] = h1[b,s,:] @ Wout^T + bout
// ---------------------------------------------------------------------------
__global__ void __launch_bounds__(256) proj_kernel(
    const float* __restrict__ Wout, const float* __restrict__ bout,
    float* __restrict__ out)
{
    extern __shared__ float smP[];
    float* ws = smP;              // [64][257]
    float* hsr = smP + 64 * 257;  // [32][257]
    const int tid = threadIdx.x;
    const int lin0 = blockIdx.x * 32;

    for (int i = tid; i < 64 * 64; i += 256) {
        int row = i >> 6, k4 = i & 63;
        float4 v = ((const float4*)(Wout + row * 256))[k4];
        float* d = ws + row * 257 + k4 * 4;
        d[0] = v.x; d[1] = v.y; d[2] = v.z; d[3] = v.w;
    }
    for (int i = tid; i < 32 * 32; i += 256) {
        int rr = i >> 5, ch = i & 31;
        int lin = lin0 + rr, b = lin >> 9, s = lin & 511;
        size_t off = (size_t)(s + 1) * 65536u + (size_t)b * 256u + (size_t)ch * 8u;
        uint4 vh = *(const uint4*)(g_h1hi + off);
        const __half* ph = (const __half*)&vh;
        float* d = hsr + rr * 257 + ch * 8;
#pragma unroll
        for (int k = 0; k < 8; ++k)
            d[k] = __half2float(ph[k]);
    }
    __syncthreads();

    const int o = tid & 63, rg = tid >> 6;
    float acc[8];
    float bb = bout[o];
#pragma unroll
    for (int ri = 0; ri < 8; ++ri) acc[ri] = bb;
    const float* wrow = ws + o * 257;
    const float* hbase = hsr + (rg * 8) * 257;
#pragma unroll 4
    for (int k = 0; k < 256; ++k) {
        float wv = wrow[k];
#pragma unroll
        for (int ri = 0; ri < 8; ++ri) acc[ri] += hbase[ri * 257 + k] * wv;
    }
#pragma unroll
    for (int ri = 0; ri < 8; ++ri) {
        int lin = lin0 + rg * 8 + ri;
        out[(unsigned)lin * 64u + o] = acc[ri];
    }
}

// ---------------------------------------------------------------------------
// kernel_launch
// ---------------------------------------------------------------------------
extern "C" void kernel_launch(void* const* d_in, const int* in_sizes, int n_in,
                              void* d_out, int out_size)
{
    const float* z    = (const float*)d_in[0];
    const float* fhw  = (const float*)d_in[1];
    const float* fhb  = (const float*)d_in[2];
    const float* fcw  = (const float*)d_in[3];
    const float* fcb  = (const float*)d_in[4];
    const float* fiw  = (const float*)d_in[5];
    const float* fib  = (const float*)d_in[6];
    const float* Wih0 = (const float*)d_in[7];
    const float* Whh0 = (const float*)d_in[8];
    const float* bih0 = (const float*)d_in[9];
    const float* bhh0 = (const float*)d_in[10];
    const float* Wih1 = (const float*)d_in[11];
    const float* Whh1 = (const float*)d_in[12];
    const float* bih1 = (const float*)d_in[13];
    const float* bhh1 = (const float*)d_in[14];
    const float* Wout = (const float*)d_in[15];
    const float* bout = (const float*)d_in[16];
    float* out = (float*)d_out;

    static int smem_set = 0;
    if (!smem_set) {
        cudaFuncSetAttribute(lstm_kernel, cudaFuncAttributeMaxDynamicSharedMemorySize, 131072);
        cudaFuncSetAttribute(proj_kernel, cudaFuncAttributeMaxDynamicSharedMemorySize, 98688);
        smem_set = 1;
    }

    init_states<<<256, 256>>>(z, fhw, fhb, fcw, fcb, fiw, fib);
    init_gx0<<<256, 256>>>(Wih0, bih0, bhh0, bih1, bhh1);
    lstm_kernel<<<96, 256, 131072>>>(Whh0, Wih1, Whh1);
    proj_kernel<<<4096, 256, 98688>>>(Wout, bout, out);
}